// round 11
// baseline (speedup 1.0000x reference)
#include <cuda_runtime.h>
#include <cuda_bf16.h>
#include <cstdint>
#include <math.h>

#define DD 512
#define SS 256
#define BB 32
#define TT 24
#define NROWS (BB*SS)   // 8192

#define CROWS 208
// dynamic smem layout (float offsets) — scan kernel
#define OFF_WC   0                          // CROWS rows x 512 bf16 = CROWS*256 floats
#define OFF_R    (CROWS*256)                // 53248
#define OFF_ADD  (OFF_R + 512)
#define OFF_TRR  (OFF_ADD + 128)
#define OFF_LP   (OFF_TRR + 128)
#define OFF_LGF  (OFF_LP + 256)
#define OFF_RED  (OFF_LGF + 256)
#define OFF_SW   (OFF_RED + 32)
#define OFF_PT   (OFF_SW + 256)
#define OFF_RN   (OFF_PT + 512)
#define OFF_MW   (OFF_RN + 128)
#define OFF_PB   (OFF_MW + 128)
#define SMEM_SCAN_FLOATS (OFF_PB + 256)     // 55840 floats = 223360 B
#define SMEM_SCAN_BYTES  (SMEM_SCAN_FLOATS*4)

// ---------------- device scratch ----------------
__device__ float g_bcat[512];
__device__ float g_co[NROWS*512];
__device__ __nv_bfloat16 g_codm[NROWS*512];
__device__ float g_qm[TT*BB*512];
__device__ float g_r[BB*512];
__device__ __nv_bfloat16 g_wbf[1024*512];          // [rm_w(512) | rr_w(512)] bf16

// ---------------- helpers ----------------
__device__ __forceinline__ float tanh_mufu(float x){
    float y;
    asm("tanh.approx.f32 %0, %1;" : "=f"(y) : "f"(x));
    return y;
}

__device__ __forceinline__ float warp_sum(float v){
#pragma unroll
    for (int o = 16; o; o >>= 1) v += __shfl_xor_sync(0xffffffffu, v, o);
    return v;
}

__device__ __forceinline__ unsigned int s2u(const void* p){
    unsigned int a;
    asm("{ .reg .u64 t; cvta.to.shared.u64 t, %1; cvt.u32.u64 %0, t; }" : "=r"(a) : "l"(p));
    return a;
}

__device__ __forceinline__ float dsmem_ld(unsigned int saddr, unsigned int rank){
    unsigned int ra; float v;
    asm volatile("mapa.shared::cluster.u32 %0, %1, %2;" : "=r"(ra) : "r"(saddr), "r"(rank));
    asm volatile("ld.shared::cluster.f32 %0, [%1];" : "=f"(v) : "r"(ra) : "memory");
    return v;
}

#define CLUSTER_SYNC() do{ \
    asm volatile("barrier.cluster.arrive.aligned;" ::: "memory"); \
    asm volatile("barrier.cluster.wait.aligned;"   ::: "memory"); }while(0)

// dot of 16 bf16 weights (2 x uint4) with 16 fp32 r values
__device__ __forceinline__ float dot16(uint4 u0, uint4 u1, const float* r){
    float s = 0.f; float2 c;
    c = __bfloat1622float2(*(const __nv_bfloat162*)&u0.x); s += c.x*r[0]  + c.y*r[1];
    c = __bfloat1622float2(*(const __nv_bfloat162*)&u0.y); s += c.x*r[2]  + c.y*r[3];
    c = __bfloat1622float2(*(const __nv_bfloat162*)&u0.z); s += c.x*r[4]  + c.y*r[5];
    c = __bfloat1622float2(*(const __nv_bfloat162*)&u0.w); s += c.x*r[6]  + c.y*r[7];
    c = __bfloat1622float2(*(const __nv_bfloat162*)&u1.x); s += c.x*r[8]  + c.y*r[9];
    c = __bfloat1622float2(*(const __nv_bfloat162*)&u1.y); s += c.x*r[10] + c.y*r[11];
    c = __bfloat1622float2(*(const __nv_bfloat162*)&u1.z); s += c.x*r[12] + c.y*r[13];
    c = __bfloat1622float2(*(const __nv_bfloat162*)&u1.w); s += c.x*r[14] + c.y*r[15];
    return s;
}

// ---------------- GEMM building blocks (unchanged) ----------------
__device__ __forceinline__ void sts16(float* As, float* Bs, int lr0, int lc4,
                                      float4 a0, float4 a1, float4 w0, float4 w1){
    As[(lc4+0)*132 + lr0]      = a0.x; As[(lc4+1)*132 + lr0]      = a0.y;
    As[(lc4+2)*132 + lr0]      = a0.z; As[(lc4+3)*132 + lr0]      = a0.w;
    As[(lc4+0)*132 + lr0 + 64] = a1.x; As[(lc4+1)*132 + lr0 + 64] = a1.y;
    As[(lc4+2)*132 + lr0 + 64] = a1.z; As[(lc4+3)*132 + lr0 + 64] = a1.w;
    Bs[(lc4+0)*132 + lr0]      = w0.x; Bs[(lc4+1)*132 + lr0]      = w0.y;
    Bs[(lc4+2)*132 + lr0]      = w0.z; Bs[(lc4+3)*132 + lr0]      = w0.w;
    Bs[(lc4+0)*132 + lr0 + 64] = w1.x; Bs[(lc4+1)*132 + lr0 + 64] = w1.y;
    Bs[(lc4+2)*132 + lr0 + 64] = w1.z; Bs[(lc4+3)*132 + lr0 + 64] = w1.w;
}

__device__ __forceinline__ void mm16(const float* As, const float* Bs,
                                     float acc[8][8], int tx, int ty){
#pragma unroll
    for (int k = 0; k < 16; k++){
        float4 af0 = *(const float4*)&As[k*132 + ty*8];
        float4 af1 = *(const float4*)&As[k*132 + ty*8 + 4];
        float4 bf0 = *(const float4*)&Bs[k*132 + tx*8];
        float4 bf1 = *(const float4*)&Bs[k*132 + tx*8 + 4];
        float av[8] = {af0.x,af0.y,af0.z,af0.w,af1.x,af1.y,af1.z,af1.w};
        float bv[8] = {bf0.x,bf0.y,bf0.z,bf0.w,bf1.x,bf1.y,bf1.z,bf1.w};
#pragma unroll
        for (int i = 0; i < 8; i++)
#pragma unroll
            for (int j = 0; j < 8; j++)
                acc[i][j] = fmaf(av[i], bv[j], acc[i][j]);
    }
}

// ---------------- prep: bcat + bf16 weight conversion ----------------
__global__ __launch_bounds__(256) void prep_all(const float* __restrict__ fc1b,
                                                const float* __restrict__ fc2b,
                                                const float* __restrict__ rm_w,
                                                const float* __restrict__ rr_w){
    int v = blockIdx.x * 256 + threadIdx.x;      // 512 blocks = 131072 threads
    if (v < 512) g_bcat[v] = fc1b[v] + fc2b[v];
    // convert: v indexes float4 over [rm_w | rr_w] (131072 float4s total)
    const float* src = (v < 65536) ? rm_w : rr_w;
    int i = v & 65535;
    float4 f = ((const float4*)src)[i];
    __nv_bfloat162 p0 = __floats2bfloat162_rn(f.x, f.y);
    __nv_bfloat162 p1 = __floats2bfloat162_rn(f.z, f.w);
    unsigned a, bcc;
    a = *(unsigned*)&p0; bcc = *(unsigned*)&p1;
    ((uint2*)g_wbf)[v] = make_uint2(a, bcc);
}

// ---------------- fused GEMM launch A (unchanged) ----------------
__global__ __launch_bounds__(256) void gemm_A(const float* __restrict__ ctx,
                                              const float* __restrict__ img,
                                              const float* __restrict__ fc1w,
                                              const float* __restrict__ fc2w,
                                              const float* __restrict__ qout,
                                              const float* __restrict__ qmw,
                                              const float* __restrict__ qmb)
{
    __shared__ __align__(16) float sh[4*2112];
    const int bid = blockIdx.x;
    const int tid = threadIdx.x;

    if (bid < 256){
        const int m0  = (bid >> 2) * 128;
        const int n0  = (bid & 3) * 128;
        const int tx  = tid & 15, ty = tid >> 4;
        const int lr0 = tid >> 2;
        const int lc4 = (tid & 3) * 4;

        const int r1 = m0 + lr0, r2 = r1 + 64;
        const int p1 = (r1 & 255)*32 + (r1 >> 8);
        const int p2 = (r2 & 255)*32 + (r2 >> 8);

        const float* A1h[2] = { ctx + (size_t)p1*512 + lc4,  img + (size_t)p1*512 + lc4 };
        const float* A2h[2] = { ctx + (size_t)p2*512 + lc4,  img + (size_t)p2*512 + lc4 };
        const float* W1h[2] = { fc1w + (size_t)(n0+lr0)*512 + lc4,
                                fc2w + (size_t)(n0+lr0)*512 + lc4 };
        const float* W2h[2] = { fc1w + (size_t)(n0+lr0+64)*512 + lc4,
                                fc2w + (size_t)(n0+lr0+64)*512 + lc4 };

        float acc[8][8] = {};
        float4 a0, a1, w0, w1;

        a0 = *(const float4*)A1h[0]; a1 = *(const float4*)A2h[0];
        w0 = *(const float4*)W1h[0]; w1 = *(const float4*)W2h[0];
        sts16(sh, sh + 2112, lr0, lc4, a0, a1, w0, w1);
        __syncthreads();

#pragma unroll 1
        for (int it = 0; it < 64; it++){
            const bool has = (it + 1 < 64);
            if (has){
                const int h  = (it+1) >> 5;
                const int kt = ((it+1) & 31) * 16;
                a0 = *(const float4*)((h ? A1h[1] : A1h[0]) + kt);
                a1 = *(const float4*)((h ? A2h[1] : A2h[0]) + kt);
                w0 = *(const float4*)((h ? W1h[1] : W1h[0]) + kt);
                w1 = *(const float4*)((h ? W2h[1] : W2h[0]) + kt);
            }
            const int cur = (it & 1) * 4224;
            mm16(sh + cur, sh + cur + 2112, acc, tx, ty);
            if (has){
                const int nxt = ((it+1) & 1) * 4224;
                sts16(sh + nxt, sh + nxt + 2112, lr0, lc4, a0, a1, w0, w1);
            }
            __syncthreads();
        }

        float4 bb0 = *(const float4*)&g_bcat[n0 + tx*8];
        float4 bb1 = *(const float4*)&g_bcat[n0 + tx*8 + 4];
        float bj[8] = {bb0.x,bb0.y,bb0.z,bb0.w,bb1.x,bb1.y,bb1.z,bb1.w};
#pragma unroll
        for (int i = 0; i < 8; i++){
            int m = m0 + ty*8 + i;
            float4 o0 = make_float4(acc[i][0]+bj[0], acc[i][1]+bj[1],
                                    acc[i][2]+bj[2], acc[i][3]+bj[3]);
            float4 o1 = make_float4(acc[i][4]+bj[4], acc[i][5]+bj[5],
                                    acc[i][6]+bj[6], acc[i][7]+bj[7]);
            *(float4*)&g_co[(size_t)m*512 + n0 + tx*8]     = o0;
            *(float4*)&g_co[(size_t)m*512 + n0 + tx*8 + 4] = o1;
        }
    } else {
        float* As = sh;            // stride 68
        float* Bs = sh + 16*68;
        const int qid = bid - 256;
        const int m0  = (qid >> 3) * 64;
        const int n0  = (qid & 7) * 64;
        const int tx  = tid & 15, ty = tid >> 4;
        const int lr0 = tid >> 2;
        const int lc4 = (tid & 3) * 4;

        float acc[4][4] = {};
        const float* A1 = qout + (size_t)(m0 + lr0)*512 + lc4;
        const float* W1 = qmw  + (size_t)(n0 + lr0)*512 + lc4;

        for (int kt = 0; kt < 512; kt += 16){
            float4 a0 = *(const float4*)(A1 + kt);
            float4 w0 = *(const float4*)(W1 + kt);
            __syncthreads();
            As[(lc4+0)*68 + lr0] = a0.x; As[(lc4+1)*68 + lr0] = a0.y;
            As[(lc4+2)*68 + lr0] = a0.z; As[(lc4+3)*68 + lr0] = a0.w;
            Bs[(lc4+0)*68 + lr0] = w0.x; Bs[(lc4+1)*68 + lr0] = w0.y;
            Bs[(lc4+2)*68 + lr0] = w0.z; Bs[(lc4+3)*68 + lr0] = w0.w;
            __syncthreads();
#pragma unroll
            for (int k = 0; k < 16; k++){
                float4 av = *(const float4*)&As[k*68 + ty*4];
                float4 bv = *(const float4*)&Bs[k*68 + tx*4];
                float aa[4] = {av.x,av.y,av.z,av.w};
                float bb[4] = {bv.x,bv.y,bv.z,bv.w};
#pragma unroll
                for (int i = 0; i < 4; i++)
#pragma unroll
                    for (int j = 0; j < 4; j++)
                        acc[i][j] = fmaf(aa[i], bb[j], acc[i][j]);
            }
        }

        float4 bq = *(const float4*)&qmb[n0 + tx*4];
        float bj[4] = {bq.x,bq.y,bq.z,bq.w};
#pragma unroll
        for (int i = 0; i < 4; i++){
            int m = m0 + ty*4 + i;
            float4 o = make_float4(acc[i][0]+bj[0], acc[i][1]+bj[1],
                                   acc[i][2]+bj[2], acc[i][3]+bj[3]);
            *(float4*)&g_qm[(size_t)m*512 + n0 + tx*4] = o;
        }
    }
}

// ---------------- codm GEMM (unchanged) ----------------
__global__ __launch_bounds__(256) void sgemm_codm(const float* __restrict__ W,
                                                  const float* __restrict__ bias)
{
    __shared__ __align__(16) float sh[4*2112];
    const int m0  = blockIdx.y * 128;
    const int n0  = blockIdx.x * 128;
    const int tid = threadIdx.x;
    const int tx  = tid & 15, ty = tid >> 4;
    const int lr0 = tid >> 2;
    const int lc4 = (tid & 3) * 4;

    const float* A1 = g_co + (size_t)(m0 + lr0) * 512 + lc4;
    const float* A2 = A1 + (size_t)64*512;
    const float* W1 = W + (size_t)(n0 + lr0) * 512 + lc4;
    const float* W2 = W1 + (size_t)64*512;

    float acc[8][8] = {};
    float4 a0 = *(const float4*)A1;
    float4 a1 = *(const float4*)A2;
    float4 w0 = *(const float4*)W1;
    float4 w1 = *(const float4*)W2;
    sts16(sh, sh + 2112, lr0, lc4, a0, a1, w0, w1);
    __syncthreads();

#pragma unroll 1
    for (int it = 0; it < 32; it++){
        const bool has = (it + 1 < 32);
        if (has){
            const int kt = (it+1) * 16;
            a0 = *(const float4*)(A1 + kt); a1 = *(const float4*)(A2 + kt);
            w0 = *(const float4*)(W1 + kt); w1 = *(const float4*)(W2 + kt);
        }
        const int cur = (it & 1) * 4224;
        mm16(sh + cur, sh + cur + 2112, acc, tx, ty);
        if (has){
            const int nxt = ((it+1) & 1) * 4224;
            sts16(sh + nxt, sh + nxt + 2112, lr0, lc4, a0, a1, w0, w1);
        }
        __syncthreads();
    }

    float4 bb0 = *(const float4*)&bias[n0 + tx*8];
    float4 bb1 = *(const float4*)&bias[n0 + tx*8 + 4];
    float bj[8] = {bb0.x,bb0.y,bb0.z,bb0.w,bb1.x,bb1.y,bb1.z,bb1.w};
#pragma unroll
    for (int i = 0; i < 8; i++){
        int m = m0 + ty*8 + i;
        __nv_bfloat162 p[4];
        p[0] = __floats2bfloat162_rn(acc[i][0]+bj[0], acc[i][1]+bj[1]);
        p[1] = __floats2bfloat162_rn(acc[i][2]+bj[2], acc[i][3]+bj[3]);
        p[2] = __floats2bfloat162_rn(acc[i][4]+bj[4], acc[i][5]+bj[5]);
        p[3] = __floats2bfloat162_rn(acc[i][6]+bj[6], acc[i][7]+bj[7]);
        *(uint4*)&g_codm[(size_t)m*512 + n0 + tx*8] = *(uint4*)p;
    }
}

// ---------------- persistent cluster scan v3: e-slice ownership, 2 syncs/step ----------------
// grid 128 = 32 batches x 4-CTA clusters, 512 thr. CTA rank owns e in [rank*128,+128):
// computes rm rows (add) AND rr rows (trr) for that slice -> both stay LOCAL.
// L computes PARTIAL logits over the local e-slice for all 256 s (separable dot).
// bf16 weights: 208/256 rows cached in smem, 48 streamed from L2 per step.
__global__ void __launch_bounds__(512, 1) __cluster_dims__(4, 1, 1)
scan_cluster(const float* __restrict__ rm_b, const float* __restrict__ rr_b,
             const float* __restrict__ ms_w, const float* __restrict__ ms_b)
{
    extern __shared__ float sm[];
    __nv_bfloat16* wc = (__nv_bfloat16*)(sm + OFF_WC);
    float* s_r   = sm + OFF_R;
    float* s_add = sm + OFF_ADD;
    float* s_trr = sm + OFF_TRR;
    float* s_lp  = sm + OFF_LP;
    float* s_lgf = sm + OFF_LGF;
    float* s_red = sm + OFF_RED;
    float* s_sw  = sm + OFF_SW;
    float* s_pt  = sm + OFF_PT;
    float* s_rn  = sm + OFF_RN;
    float* s_mw  = sm + OFF_MW;
    float* s_pb  = sm + OFF_PB;

    const int tid = threadIdx.x, lane = tid & 31, warp = tid >> 5;   // warp 0..15
    unsigned int rank; asm("mov.u32 %0, %%cluster_ctarank;" : "=r"(rank));
    const int b = blockIdx.x >> 2;

    // global weight row bases for this CTA's 256 rows (rm slice + rr slice)
    const __nv_bfloat16* grm = g_wbf + (size_t)(rank*128)*512;
    const __nv_bfloat16* grr = g_wbf + (size_t)(512 + rank*128)*512;

    // ---- init: cache 208 rows (uint4 units: 64 per row) ----
    for (int idx = tid; idx < CROWS*64; idx += 512){
        int row = idx >> 6, c = idx & 63;
        const __nv_bfloat16* src = (row < 128) ? (grm + (size_t)row*512)
                                               : (grr + (size_t)(row-128)*512);
        ((uint4*)wc)[idx] = ((const uint4*)src)[c];
    }
    if (tid < 256) s_pb[tid] = (tid < 128) ? rm_b[rank*128 + tid]
                                           : rr_b[rank*128 + tid - 128];
    if (tid < 128) s_mw[tid] = ms_w[rank*128 + tid];
    s_r[tid] = 0.f;
    const float msb0 = ms_b[0];
    __syncthreads();

    for (int t = 0; t < TT; t++){
        // ================= P: 256 rows (warps 0-7: rm->add, 8-15: rr->trr), local only
        float rreg[16];
#pragma unroll
        for (int i = 0; i < 4; i++)
            ((float4*)rreg)[i] = *(const float4*)&s_r[lane*16 + i*4];

        float qv[4] = {0.f,0.f,0.f,0.f};
        if (warp < 8 && lane < 4){
#pragma unroll
            for (int g = 0; g < 4; g++)
                qv[g] = g_qm[(size_t)(t*BB + b)*512 + rank*128 + warp*16 + g*4 + lane];
        }

        if (warp < 13){
            // fully cached rows
#pragma unroll
            for (int g = 0; g < 4; g++){
                float sums[4];
#pragma unroll
                for (int q = 0; q < 4; q++){
                    const __nv_bfloat16* wp = wc + (size_t)(warp*16 + g*4 + q)*512 + lane*16;
                    uint4 u0 = *(const uint4*)wp;
                    uint4 u1 = *(const uint4*)(wp + 8);
                    sums[q] = dot16(u0, u1, rreg);
                }
#pragma unroll
                for (int q = 0; q < 4; q++) sums[q] = warp_sum(sums[q]);
                if (lane < 4){
                    float v = (lane==0)?sums[0]:(lane==1)?sums[1]:(lane==2)?sums[2]:sums[3];
                    int row = warp*16 + g*4 + lane;
                    v += s_pb[row];
                    if (warp < 8) s_add[row]       = v + qv[g];
                    else          s_trr[row - 128] = tanh_mufu(v);
                }
            }
        } else {
            // streamed rows (rr rows 208..255): batch the 8 LDGs per group
#pragma unroll
            for (int g = 0; g < 4; g++){
                uint4 u[4][2];
#pragma unroll
                for (int q = 0; q < 4; q++){
                    const __nv_bfloat16* wp = grr + (size_t)(warp*16 + g*4 + q - 128)*512 + lane*16;
                    u[q][0] = *(const uint4*)wp;
                    u[q][1] = *(const uint4*)(wp + 8);
                }
                float sums[4];
#pragma unroll
                for (int q = 0; q < 4; q++) sums[q] = dot16(u[q][0], u[q][1], rreg);
#pragma unroll
                for (int q = 0; q < 4; q++) sums[q] = warp_sum(sums[q]);
                if (lane < 4){
                    float v = (lane==0)?sums[0]:(lane==1)?sums[1]:(lane==2)?sums[2]:sums[3];
                    int row = warp*16 + g*4 + lane;
                    s_trr[row - 128] = tanh_mufu(v + s_pb[row]);
                }
            }
        }
        __syncthreads();

        // ================= L: partial logits over local e-slice for all 256 s
        {
            float areg[4], mreg[4];
#pragma unroll
            for (int i = 0; i < 4; i++){
                areg[i] = s_add[lane*4 + i];
                mreg[i] = s_mw[lane*4 + i];
            }
#pragma unroll
            for (int g = 0; g < 4; g++){
                int s0 = warp*16 + g*4;
                float a4[4];
#pragma unroll
                for (int q = 0; q < 4; q++){
                    const __nv_bfloat16* cd = g_codm + (size_t)(b*256 + s0 + q)*512
                                            + rank*128 + lane*4;
                    uint2 u = *(const uint2*)cd;
                    float2 c01 = __bfloat1622float2(*(const __nv_bfloat162*)&u.x);
                    float2 c23 = __bfloat1622float2(*(const __nv_bfloat162*)&u.y);
                    a4[q] = tanh_mufu(c01.x + areg[0]) * mreg[0]
                          + tanh_mufu(c01.y + areg[1]) * mreg[1]
                          + tanh_mufu(c23.x + areg[2]) * mreg[2]
                          + tanh_mufu(c23.y + areg[3]) * mreg[3];
                }
#pragma unroll
                for (int q = 0; q < 4; q++) a4[q] = warp_sum(a4[q]);
                if (lane < 4){
                    float v = (lane==0)?a4[0]:(lane==1)?a4[1]:(lane==2)?a4[2]:a4[3];
                    s_lp[s0 + lane] = v;
                }
            }
        }
        CLUSTER_SYNC();                         // all partial logits visible (#1)

        // ================= X: sum partials -> full logits (redundant per CTA)
        if (tid < 256){
            unsigned int sa = s2u(&s_lp[tid]);
            float v = s_lp[tid] + msb0
                    + dsmem_ld(sa, (rank+1)&3u)
                    + dsmem_ld(sa, (rank+2)&3u)
                    + dsmem_ld(sa, (rank+3)&3u);
            s_lgf[tid] = v;
        }
        __syncthreads();

        // ================= softmax over 256 (512-thread duplicate)
        {
            float l = s_lgf[tid & 255];
            float m = l;
#pragma unroll
            for (int o = 16; o; o >>= 1) m = fmaxf(m, __shfl_xor_sync(0xffffffffu, m, o));
            if (lane == 0) s_red[warp] = m;
            __syncthreads();
            float mx = s_red[0];
#pragma unroll
            for (int i = 1; i < 16; i++) mx = fmaxf(mx, s_red[i]);
            float ex = __expf(l - mx);
            float smm = warp_sum(ex);
            if (lane == 0) s_red[16 + warp] = smm;
            __syncthreads();
            float tot = s_red[16];
#pragma unroll
            for (int i = 17; i < 32; i++) tot += s_red[i];
            tot *= 0.5f;                         // duplicated counting
            s_sw[tid & 255] = ex * (1.0f / tot);
        }
        __syncthreads();

        // ================= U: e-slice update; trr LOCAL
        {
            int e  = (int)rank*128 + (tid & 127);
            int sq = tid >> 7;
            const float* cb = g_co + (size_t)(b*256 + sq*64)*512 + e;
            const float* wv = s_sw + sq*64;
            float acc = 0.f;
#pragma unroll 16
            for (int s = 0; s < 64; s++)
                acc = fmaf(wv[s], cb[(size_t)s*512], acc);
            s_pt[tid] = acc;
            __syncthreads();
            if (tid < 128){
                float v = s_pt[tid] + s_pt[tid+128] + s_pt[tid+256] + s_pt[tid+384]
                        + s_trr[tid];
                s_rn[tid] = v;
                if (t == TT-1) g_r[b*512 + (int)rank*128 + tid] = v;
            }
        }
        CLUSTER_SYNC();                         // s_rn visible (#2)

        if (t < TT-1){
            s_r[tid] = dsmem_ld(s2u(&s_rn[tid & 127]), (unsigned int)(tid >> 7));
            __syncthreads();
        }
    }

    CLUSTER_SYNC();   // no CTA exits while a peer may still read its SMEM
}

// ---------------- final: g = rg(r) + qg(qh) ----------------
__global__ __launch_bounds__(256) void final_g(const float* __restrict__ rg_w,
                                               const float* __restrict__ rg_b,
                                               const float* __restrict__ qg_w,
                                               const float* __restrict__ qg_b,
                                               const float* __restrict__ qh,
                                               float* __restrict__ out)
{
    __shared__ __align__(16) float sr[512];
    __shared__ __align__(16) float sq[512];
    int bx  = blockIdx.x;
    int b   = bx >> 6, ec = bx & 63;
    int tid = threadIdx.x, lane = tid & 31, warp = tid >> 5;
    sr[tid]       = g_r[b*512 + tid];
    sr[tid + 256] = g_r[b*512 + tid + 256];
    sq[tid]       = qh[b*512 + tid];
    sq[tid + 256] = qh[b*512 + tid + 256];
    __syncthreads();
    int e = ec*8 + warp;
    const float* w1 = rg_w + e*512;
    const float* w2 = qg_w + e*512;
    float s = 0.f;
#pragma unroll
    for (int i = 0; i < 4; i++){
        int k = i*128 + lane*4;
        float4 a = *(const float4*)(w1 + k); float4 x = *(const float4*)(sr + k);
        float4 c = *(const float4*)(w2 + k); float4 y = *(const float4*)(sq + k);
        s += a.x*x.x + a.y*x.y + a.z*x.z + a.w*x.w;
        s += c.x*y.x + c.y*y.y + c.z*y.z + c.w*y.w;
    }
    s = warp_sum(s);
    if (lane == 0) out[b*512 + e] = s + rg_b[e] + qg_b[e];
}

// ---------------- host launch ----------------
extern "C" void kernel_launch(void* const* d_in, const int* in_sizes, int n_in,
                              void* d_out, int out_size)
{
    const float* ctx  = (const float*)d_in[0];
    const float* qout = (const float*)d_in[2];
    const float* qh   = (const float*)d_in[3];
    const float* img  = (const float*)d_in[4];
    const float* fc1w = (const float*)d_in[6];  const float* fc1b = (const float*)d_in[7];
    const float* fc2w = (const float*)d_in[8];  const float* fc2b = (const float*)d_in[9];
    const float* dmw  = (const float*)d_in[10]; const float* dmb  = (const float*)d_in[11];
    const float* msw  = (const float*)d_in[12]; const float* msb  = (const float*)d_in[13];
    const float* rmw  = (const float*)d_in[14]; const float* rmb  = (const float*)d_in[15];
    const float* qmw  = (const float*)d_in[16]; const float* qmb  = (const float*)d_in[17];
    const float* rrw  = (const float*)d_in[18]; const float* rrb  = (const float*)d_in[19];
    const float* rgw  = (const float*)d_in[20]; const float* rgb  = (const float*)d_in[21];
    const float* qgw  = (const float*)d_in[22]; const float* qgb  = (const float*)d_in[23];

    cudaFuncSetAttribute(scan_cluster, cudaFuncAttributeMaxDynamicSharedMemorySize,
                         SMEM_SCAN_BYTES);

    prep_all<<<512, 256>>>(fc1b, fc2b, rmw, rrw);

    // co (fused perm+concat GEMM, pipelined) + qm GEMM in ONE launch
    gemm_A<<<352, 256>>>(ctx, img, fc1w, fc2w, qout, qmw, qmb);

    // codm(bf16) = co @ dm_w^T + dm_b  (pipelined)
    sgemm_codm<<<dim3(4, 64), 256>>>(dmw, dmb);

    // ENTIRE scan: 32 independent 4-CTA clusters, 2 cluster syncs/step
    scan_cluster<<<128, 512, SMEM_SCAN_BYTES>>>(rmb, rrb, msw, msb);

    final_g<<<2048, 256>>>(rgw, rgb, qgw, qgb, qh, (float*)d_out);
}

// round 14
// speedup vs baseline: 1.0221x; 1.0221x over previous
#include <cuda_runtime.h>
#include <cuda_bf16.h>
#include <cstdint>
#include <math.h>

#define DD 512
#define SS 256
#define BB 32
#define TT 24
#define NROWS (BB*SS)   // 8192

#define CROWS 208
// dynamic smem layout (float offsets) — scan kernel
#define OFF_WC   0
#define OFF_R    (CROWS*256)
#define OFF_ADD  (OFF_R + 512)
#define OFF_TRR  (OFF_ADD + 128)
#define OFF_LP   (OFF_TRR + 128)
#define OFF_LGF  (OFF_LP + 256)
#define OFF_RED  (OFF_LGF + 256)
#define OFF_SW   (OFF_RED + 32)
#define OFF_PT   (OFF_SW + 256)
#define OFF_RN   (OFF_PT + 512)
#define OFF_MW   (OFF_RN + 128)
#define OFF_PB   (OFF_MW + 128)
#define SMEM_SCAN_FLOATS (OFF_PB + 256)
#define SMEM_SCAN_BYTES  (SMEM_SCAN_FLOATS*4)

#define MPAD 72
#define CODM_SMEM_BYTES (4*128*MPAD*2)   // Ah,Al,Bh,Bl tiles = 73728 B

// ---------------- device scratch ----------------
__device__ float g_bcat[512];
__device__ float g_co[NROWS*512];
__device__ __nv_bfloat16 g_cohi[NROWS*512];
__device__ __nv_bfloat16 g_colo[NROWS*512];
__device__ __nv_bfloat16 g_codm[NROWS*512];
__device__ float g_qm[TT*BB*512];
__device__ float g_r[BB*512];
__device__ __nv_bfloat16 g_wbf[1024*512];          // [rm_w | rr_w] bf16 (scan)
__device__ __nv_bfloat16 g_dmhi[512*512];
__device__ __nv_bfloat16 g_dmlo[512*512];

// ---------------- helpers ----------------
__device__ __forceinline__ float tanh_mufu(float x){
    float y;
    asm("tanh.approx.f32 %0, %1;" : "=f"(y) : "f"(x));
    return y;
}

__device__ __forceinline__ float warp_sum(float v){
#pragma unroll
    for (int o = 16; o; o >>= 1) v += __shfl_xor_sync(0xffffffffu, v, o);
    return v;
}

__device__ __forceinline__ unsigned int s2u(const void* p){
    unsigned int a;
    asm("{ .reg .u64 t; cvta.to.shared.u64 t, %1; cvt.u32.u64 %0, t; }" : "=r"(a) : "l"(p));
    return a;
}

__device__ __forceinline__ float dsmem_ld(unsigned int saddr, unsigned int rank){
    unsigned int ra; float v;
    asm volatile("mapa.shared::cluster.u32 %0, %1, %2;" : "=r"(ra) : "r"(saddr), "r"(rank));
    asm volatile("ld.shared::cluster.f32 %0, [%1];" : "=f"(v) : "r"(ra) : "memory");
    return v;
}

#define CLUSTER_SYNC() do{ \
    asm volatile("barrier.cluster.arrive.aligned;" ::: "memory"); \
    asm volatile("barrier.cluster.wait.aligned;"   ::: "memory"); }while(0)

// dot of 16 bf16 weights with 16 fp32 r values
__device__ __forceinline__ float dot16(uint4 u0, uint4 u1, const float* r){
    float s = 0.f; float2 c;
    c = __bfloat1622float2(*(const __nv_bfloat162*)&u0.x); s += c.x*r[0]  + c.y*r[1];
    c = __bfloat1622float2(*(const __nv_bfloat162*)&u0.y); s += c.x*r[2]  + c.y*r[3];
    c = __bfloat1622float2(*(const __nv_bfloat162*)&u0.z); s += c.x*r[4]  + c.y*r[5];
    c = __bfloat1622float2(*(const __nv_bfloat162*)&u0.w); s += c.x*r[6]  + c.y*r[7];
    c = __bfloat1622float2(*(const __nv_bfloat162*)&u1.x); s += c.x*r[8]  + c.y*r[9];
    c = __bfloat1622float2(*(const __nv_bfloat162*)&u1.y); s += c.x*r[10] + c.y*r[11];
    c = __bfloat1622float2(*(const __nv_bfloat162*)&u1.z); s += c.x*r[12] + c.y*r[13];
    c = __bfloat1622float2(*(const __nv_bfloat162*)&u1.w); s += c.x*r[14] + c.y*r[15];
    return s;
}

// ---------------- GEMM building blocks ----------------
__device__ __forceinline__ void sts16(float* As, float* Bs, int lr0, int lc4,
                                      float4 a0, float4 a1, float4 w0, float4 w1){
    As[(lc4+0)*132 + lr0]      = a0.x; As[(lc4+1)*132 + lr0]      = a0.y;
    As[(lc4+2)*132 + lr0]      = a0.z; As[(lc4+3)*132 + lr0]      = a0.w;
    As[(lc4+0)*132 + lr0 + 64] = a1.x; As[(lc4+1)*132 + lr0 + 64] = a1.y;
    As[(lc4+2)*132 + lr0 + 64] = a1.z; As[(lc4+3)*132 + lr0 + 64] = a1.w;
    Bs[(lc4+0)*132 + lr0]      = w0.x; Bs[(lc4+1)*132 + lr0]      = w0.y;
    Bs[(lc4+2)*132 + lr0]      = w0.z; Bs[(lc4+3)*132 + lr0]      = w0.w;
    Bs[(lc4+0)*132 + lr0 + 64] = w1.x; Bs[(lc4+1)*132 + lr0 + 64] = w1.y;
    Bs[(lc4+2)*132 + lr0 + 64] = w1.z; Bs[(lc4+3)*132 + lr0 + 64] = w1.w;
}

__device__ __forceinline__ void mm16(const float* As, const float* Bs,
                                     float acc[8][8], int tx, int ty){
#pragma unroll
    for (int k = 0; k < 16; k++){
        float4 af0 = *(const float4*)&As[k*132 + ty*8];
        float4 af1 = *(const float4*)&As[k*132 + ty*8 + 4];
        float4 bf0 = *(const float4*)&Bs[k*132 + tx*8];
        float4 bf1 = *(const float4*)&Bs[k*132 + tx*8 + 4];
        float av[8] = {af0.x,af0.y,af0.z,af0.w,af1.x,af1.y,af1.z,af1.w};
        float bv[8] = {bf0.x,bf0.y,bf0.z,bf0.w,bf1.x,bf1.y,bf1.z,bf1.w};
#pragma unroll
        for (int i = 0; i < 8; i++)
#pragma unroll
            for (int j = 0; j < 8; j++)
                acc[i][j] = fmaf(av[i], bv[j], acc[i][j]);
    }
}

// ---------------- prep: bcat + bf16 conversions (rm|rr scan; dm hi/lo) ----------------
__global__ __launch_bounds__(256) void prep_all(const float* __restrict__ fc1b,
                                                const float* __restrict__ fc2b,
                                                const float* __restrict__ rm_w,
                                                const float* __restrict__ rr_w,
                                                const float* __restrict__ dm_w){
    int v = blockIdx.x * 256 + threadIdx.x;      // 768 blocks = 196608
    if (v < 512) g_bcat[v] = fc1b[v] + fc2b[v];
    if (v < 131072){
        const float* src = (v < 65536) ? rm_w : rr_w;
        __nv_bfloat16* dst = (v < 65536) ? g_wbf : (g_wbf + (size_t)512*512);
        int i = v & 65535;
        float4 f = ((const float4*)src)[i];
        __nv_bfloat162 p0 = __floats2bfloat162_rn(f.x, f.y);
        __nv_bfloat162 p1 = __floats2bfloat162_rn(f.z, f.w);
        ((uint2*)dst)[i] = make_uint2(*(unsigned*)&p0, *(unsigned*)&p1);
    } else {
        int i = v - 131072;                      // 0..65535
        float4 f = ((const float4*)dm_w)[i];
        float fv[4] = {f.x, f.y, f.z, f.w};
        __nv_bfloat16 h[4], l[4];
#pragma unroll
        for (int j = 0; j < 4; j++){
            h[j] = __float2bfloat16(fv[j]);
            l[j] = __float2bfloat16(fv[j] - __bfloat162float(h[j]));
        }
        ((uint2*)g_dmhi)[i] = *(uint2*)h;
        ((uint2*)g_dmlo)[i] = *(uint2*)l;
    }
}

// ---------------- fused GEMM launch A (+ hi/lo bf16 co split) ----------------
__global__ __launch_bounds__(256) void gemm_A(const float* __restrict__ ctx,
                                              const float* __restrict__ img,
                                              const float* __restrict__ fc1w,
                                              const float* __restrict__ fc2w,
                                              const float* __restrict__ qout,
                                              const float* __restrict__ qmw,
                                              const float* __restrict__ qmb)
{
    __shared__ __align__(16) float sh[4*2112];
    const int bid = blockIdx.x;
    const int tid = threadIdx.x;

    if (bid < 256){
        const int m0  = (bid >> 2) * 128;
        const int n0  = (bid & 3) * 128;
        const int tx  = tid & 15, ty = tid >> 4;
        const int lr0 = tid >> 2;
        const int lc4 = (tid & 3) * 4;

        const int r1 = m0 + lr0, r2 = r1 + 64;
        const int p1 = (r1 & 255)*32 + (r1 >> 8);
        const int p2 = (r2 & 255)*32 + (r2 >> 8);

        const float* A1h[2] = { ctx + (size_t)p1*512 + lc4,  img + (size_t)p1*512 + lc4 };
        const float* A2h[2] = { ctx + (size_t)p2*512 + lc4,  img + (size_t)p2*512 + lc4 };
        const float* W1h[2] = { fc1w + (size_t)(n0+lr0)*512 + lc4,
                                fc2w + (size_t)(n0+lr0)*512 + lc4 };
        const float* W2h[2] = { fc1w + (size_t)(n0+lr0+64)*512 + lc4,
                                fc2w + (size_t)(n0+lr0+64)*512 + lc4 };

        float acc[8][8] = {};
        float4 a0, a1, w0, w1;

        a0 = *(const float4*)A1h[0]; a1 = *(const float4*)A2h[0];
        w0 = *(const float4*)W1h[0]; w1 = *(const float4*)W2h[0];
        sts16(sh, sh + 2112, lr0, lc4, a0, a1, w0, w1);
        __syncthreads();

#pragma unroll 1
        for (int it = 0; it < 64; it++){
            const bool has = (it + 1 < 64);
            if (has){
                const int h  = (it+1) >> 5;
                const int kt = ((it+1) & 31) * 16;
                a0 = *(const float4*)((h ? A1h[1] : A1h[0]) + kt);
                a1 = *(const float4*)((h ? A2h[1] : A2h[0]) + kt);
                w0 = *(const float4*)((h ? W1h[1] : W1h[0]) + kt);
                w1 = *(const float4*)((h ? W2h[1] : W2h[0]) + kt);
            }
            const int cur = (it & 1) * 4224;
            mm16(sh + cur, sh + cur + 2112, acc, tx, ty);
            if (has){
                const int nxt = ((it+1) & 1) * 4224;
                sts16(sh + nxt, sh + nxt + 2112, lr0, lc4, a0, a1, w0, w1);
            }
            __syncthreads();
        }

        float4 bb0 = *(const float4*)&g_bcat[n0 + tx*8];
        float4 bb1 = *(const float4*)&g_bcat[n0 + tx*8 + 4];
        float bj[8] = {bb0.x,bb0.y,bb0.z,bb0.w,bb1.x,bb1.y,bb1.z,bb1.w};
#pragma unroll
        for (int i = 0; i < 8; i++){
            int m = m0 + ty*8 + i;
            float vals[8];
#pragma unroll
            for (int j = 0; j < 8; j++) vals[j] = acc[i][j] + bj[j];
            *(float4*)&g_co[(size_t)m*512 + n0 + tx*8]     = make_float4(vals[0],vals[1],vals[2],vals[3]);
            *(float4*)&g_co[(size_t)m*512 + n0 + tx*8 + 4] = make_float4(vals[4],vals[5],vals[6],vals[7]);
            __nv_bfloat16 h[8], l[8];
#pragma unroll
            for (int j = 0; j < 8; j++){
                h[j] = __float2bfloat16(vals[j]);
                l[j] = __float2bfloat16(vals[j] - __bfloat162float(h[j]));
            }
            *(uint4*)&g_cohi[(size_t)m*512 + n0 + tx*8] = *(uint4*)h;
            *(uint4*)&g_colo[(size_t)m*512 + n0 + tx*8] = *(uint4*)l;
        }
    } else {
        float* As = sh;            // stride 68
        float* Bs = sh + 16*68;
        const int qid = bid - 256;
        const int m0  = (qid >> 3) * 64;
        const int n0  = (qid & 7) * 64;
        const int tx  = tid & 15, ty = tid >> 4;
        const int lr0 = tid >> 2;
        const int lc4 = (tid & 3) * 4;

        float acc[4][4] = {};
        const float* A1 = qout + (size_t)(m0 + lr0)*512 + lc4;
        const float* W1 = qmw  + (size_t)(n0 + lr0)*512 + lc4;

        for (int kt = 0; kt < 512; kt += 16){
            float4 a0 = *(const float4*)(A1 + kt);
            float4 w0 = *(const float4*)(W1 + kt);
            __syncthreads();
            As[(lc4+0)*68 + lr0] = a0.x; As[(lc4+1)*68 + lr0] = a0.y;
            As[(lc4+2)*68 + lr0] = a0.z; As[(lc4+3)*68 + lr0] = a0.w;
            Bs[(lc4+0)*68 + lr0] = w0.x; Bs[(lc4+1)*68 + lr0] = w0.y;
            Bs[(lc4+2)*68 + lr0] = w0.z; Bs[(lc4+3)*68 + lr0] = w0.w;
            __syncthreads();
#pragma unroll
            for (int k = 0; k < 16; k++){
                float4 av = *(const float4*)&As[k*68 + ty*4];
                float4 bv = *(const float4*)&Bs[k*68 + tx*4];
                float aa[4] = {av.x,av.y,av.z,av.w};
                float bb[4] = {bv.x,bv.y,bv.z,bv.w};
#pragma unroll
                for (int i = 0; i < 4; i++)
#pragma unroll
                    for (int j = 0; j < 4; j++)
                        acc[i][j] = fmaf(aa[i], bb[j], acc[i][j]);
            }
        }

        float4 bq = *(const float4*)&qmb[n0 + tx*4];
        float bj[4] = {bq.x,bq.y,bq.z,bq.w};
#pragma unroll
        for (int i = 0; i < 4; i++){
            int m = m0 + ty*4 + i;
            float4 o = make_float4(acc[i][0]+bj[0], acc[i][1]+bj[1],
                                   acc[i][2]+bj[2], acc[i][3]+bj[3]);
            *(float4*)&g_qm[(size_t)m*512 + n0 + tx*4] = o;
        }
    }
}

// ---------------- codm via split-bf16 mma.sync (Ah·Bh + Al·Bh + Ah·Bl) ----------------
__global__ __launch_bounds__(256) void codm_mma(const float* __restrict__ bias)
{
    extern __shared__ __nv_bfloat16 smb[];
    __nv_bfloat16* sAh = smb;
    __nv_bfloat16* sAl = smb + 128*MPAD;
    __nv_bfloat16* sBh = smb + 2*128*MPAD;
    __nv_bfloat16* sBl = smb + 3*128*MPAD;

    const int tid  = threadIdx.x;
    const int warp = tid >> 5, lane = tid & 31;
    const int m0 = (int)(blockIdx.x >> 2) * 128;
    const int n0 = (int)(blockIdx.x & 3) * 128;
    const int wr = warp >> 1;          // m offset wr*32
    const int wc = warp & 1;           // n offset wc*64

    float acc[2][8][4];
#pragma unroll
    for (int i = 0; i < 2; i++)
#pragma unroll
        for (int j = 0; j < 8; j++)
#pragma unroll
            for (int k = 0; k < 4; k++) acc[i][j][k] = 0.f;

    const int ldrow = lane & 15;
    const int ldcol = (lane >> 4) * 8;

#pragma unroll 1
    for (int kc = 0; kc < 8; kc++){
#pragma unroll
        for (int t = 0; t < 4; t++){
            int i = tid + t*256;
            int r = i >> 3, c = (i & 7) * 8;
            size_t ga = (size_t)(m0 + r)*512 + kc*64 + c;
            size_t gb = (size_t)(n0 + r)*512 + kc*64 + c;
            *(uint4*)&sAh[r*MPAD + c] = *(const uint4*)&g_cohi[ga];
            *(uint4*)&sAl[r*MPAD + c] = *(const uint4*)&g_colo[ga];
            *(uint4*)&sBh[r*MPAD + c] = *(const uint4*)&g_dmhi[gb];
            *(uint4*)&sBl[r*MPAD + c] = *(const uint4*)&g_dmlo[gb];
        }
        __syncthreads();

#pragma unroll
        for (int ks = 0; ks < 4; ks++){
            unsigned int ah[2][4], al[2][4];
#pragma unroll
            for (int mt = 0; mt < 2; mt++){
                unsigned int adh = s2u(&sAh[(wr*32 + mt*16 + ldrow)*MPAD + ks*16 + ldcol]);
                asm volatile("ldmatrix.sync.aligned.m8n8.x4.shared.b16 {%0,%1,%2,%3}, [%4];"
                             : "=r"(ah[mt][0]), "=r"(ah[mt][1]), "=r"(ah[mt][2]), "=r"(ah[mt][3])
                             : "r"(adh));
                unsigned int adl = s2u(&sAl[(wr*32 + mt*16 + ldrow)*MPAD + ks*16 + ldcol]);
                asm volatile("ldmatrix.sync.aligned.m8n8.x4.shared.b16 {%0,%1,%2,%3}, [%4];"
                             : "=r"(al[mt][0]), "=r"(al[mt][1]), "=r"(al[mt][2]), "=r"(al[mt][3])
                             : "r"(adl));
            }
            unsigned int bfr[8][2];
            // --- Bh: Ah·Bh and Al·Bh ---
#pragma unroll
            for (int nb = 0; nb < 4; nb++){
                unsigned int bd = s2u(&sBh[(wc*64 + nb*16 + ldrow)*MPAD + ks*16 + ldcol]);
                unsigned int r0, r1, r2, r3;
                asm volatile("ldmatrix.sync.aligned.m8n8.x4.shared.b16 {%0,%1,%2,%3}, [%4];"
                             : "=r"(r0), "=r"(r1), "=r"(r2), "=r"(r3) : "r"(bd));
                bfr[nb*2][0]   = r0; bfr[nb*2][1]   = r2;
                bfr[nb*2+1][0] = r1; bfr[nb*2+1][1] = r3;
            }
#pragma unroll
            for (int mt = 0; mt < 2; mt++)
#pragma unroll
                for (int nt = 0; nt < 8; nt++){
                    asm volatile(
                        "mma.sync.aligned.m16n8k16.row.col.f32.bf16.bf16.f32 "
                        "{%0,%1,%2,%3}, {%4,%5,%6,%7}, {%8,%9}, {%0,%1,%2,%3};"
                        : "+f"(acc[mt][nt][0]), "+f"(acc[mt][nt][1]),
                          "+f"(acc[mt][nt][2]), "+f"(acc[mt][nt][3])
                        : "r"(ah[mt][0]), "r"(ah[mt][1]), "r"(ah[mt][2]), "r"(ah[mt][3]),
                          "r"(bfr[nt][0]), "r"(bfr[nt][1]));
                    asm volatile(
                        "mma.sync.aligned.m16n8k16.row.col.f32.bf16.bf16.f32 "
                        "{%0,%1,%2,%3}, {%4,%5,%6,%7}, {%8,%9}, {%0,%1,%2,%3};"
                        : "+f"(acc[mt][nt][0]), "+f"(acc[mt][nt][1]),
                          "+f"(acc[mt][nt][2]), "+f"(acc[mt][nt][3])
                        : "r"(al[mt][0]), "r"(al[mt][1]), "r"(al[mt][2]), "r"(al[mt][3]),
                          "r"(bfr[nt][0]), "r"(bfr[nt][1]));
                }
            // --- Bl: Ah·Bl ---
#pragma unroll
            for (int nb = 0; nb < 4; nb++){
                unsigned int bd = s2u(&sBl[(wc*64 + nb*16 + ldrow)*MPAD + ks*16 + ldcol]);
                unsigned int r0, r1, r2, r3;
                asm volatile("ldmatrix.sync.aligned.m8n8.x4.shared.b16 {%0,%1,%2,%3}, [%4];"
                             : "=r"(r0), "=r"(r1), "=r"(r2), "=r"(r3) : "r"(bd));
                bfr[nb*2][0]   = r0; bfr[nb*2][1]   = r2;
                bfr[nb*2+1][0] = r1; bfr[nb*2+1][1] = r3;
            }
#pragma unroll
            for (int mt = 0; mt < 2; mt++)
#pragma unroll
                for (int nt = 0; nt < 8; nt++){
                    asm volatile(
                        "mma.sync.aligned.m16n8k16.row.col.f32.bf16.bf16.f32 "
                        "{%0,%1,%2,%3}, {%4,%5,%6,%7}, {%8,%9}, {%0,%1,%2,%3};"
                        : "+f"(acc[mt][nt][0]), "+f"(acc[mt][nt][1]),
                          "+f"(acc[mt][nt][2]), "+f"(acc[mt][nt][3])
                        : "r"(ah[mt][0]), "r"(ah[mt][1]), "r"(ah[mt][2]), "r"(ah[mt][3]),
                          "r"(bfr[nt][0]), "r"(bfr[nt][1]));
                }
        }
        __syncthreads();
    }

    const int g  = lane >> 2;
    const int cc = (lane & 3) * 2;
#pragma unroll
    for (int mt = 0; mt < 2; mt++){
#pragma unroll
        for (int nt = 0; nt < 8; nt++){
            int n = n0 + wc*64 + nt*8 + cc;
            float b0 = bias[n], b1 = bias[n+1];
            int r0 = m0 + wr*32 + mt*16 + g;
            __nv_bfloat162 p0 = __floats2bfloat162_rn(acc[mt][nt][0] + b0,
                                                      acc[mt][nt][1] + b1);
            *(__nv_bfloat162*)&g_codm[(size_t)r0*512 + n] = p0;
            __nv_bfloat162 p1 = __floats2bfloat162_rn(acc[mt][nt][2] + b0,
                                                      acc[mt][nt][3] + b1);
            *(__nv_bfloat162*)&g_codm[(size_t)(r0+8)*512 + n] = p1;
        }
    }
}

// ---------------- persistent cluster scan (unchanged) ----------------
__global__ void __launch_bounds__(512, 1) __cluster_dims__(4, 1, 1)
scan_cluster(const float* __restrict__ rm_b, const float* __restrict__ rr_b,
             const float* __restrict__ ms_w, const float* __restrict__ ms_b)
{
    extern __shared__ float sm[];
    __nv_bfloat16* wc = (__nv_bfloat16*)(sm + OFF_WC);
    float* s_r   = sm + OFF_R;
    float* s_add = sm + OFF_ADD;
    float* s_trr = sm + OFF_TRR;
    float* s_lp  = sm + OFF_LP;
    float* s_lgf = sm + OFF_LGF;
    float* s_red = sm + OFF_RED;
    float* s_sw  = sm + OFF_SW;
    float* s_pt  = sm + OFF_PT;
    float* s_rn  = sm + OFF_RN;
    float* s_mw  = sm + OFF_MW;
    float* s_pb  = sm + OFF_PB;

    const int tid = threadIdx.x, lane = tid & 31, warp = tid >> 5;
    unsigned int rank; asm("mov.u32 %0, %%cluster_ctarank;" : "=r"(rank));
    const int b = blockIdx.x >> 2;

    const __nv_bfloat16* grm = g_wbf + (size_t)(rank*128)*512;
    const __nv_bfloat16* grr = g_wbf + (size_t)(512 + rank*128)*512;

    for (int idx = tid; idx < CROWS*64; idx += 512){
        int row = idx >> 6, c = idx & 63;
        const __nv_bfloat16* src = (row < 128) ? (grm + (size_t)row*512)
                                               : (grr + (size_t)(row-128)*512);
        ((uint4*)wc)[idx] = ((const uint4*)src)[c];
    }
    if (tid < 256) s_pb[tid] = (tid < 128) ? rm_b[rank*128 + tid]
                                           : rr_b[rank*128 + tid - 128];
    if (tid < 128) s_mw[tid] = ms_w[rank*128 + tid];
    s_r[tid] = 0.f;
    const float msb0 = ms_b[0];
    __syncthreads();

    for (int t = 0; t < TT; t++){
        float rreg[16];
#pragma unroll
        for (int i = 0; i < 4; i++)
            ((float4*)rreg)[i] = *(const float4*)&s_r[lane*16 + i*4];

        float qv[4] = {0.f,0.f,0.f,0.f};
        if (warp < 8 && lane < 4){
#pragma unroll
            for (int g = 0; g < 4; g++)
                qv[g] = g_qm[(size_t)(t*BB + b)*512 + rank*128 + warp*16 + g*4 + lane];
        }

        if (warp < 13){
#pragma unroll
            for (int g = 0; g < 4; g++){
                float sums[4];
#pragma unroll
                for (int q = 0; q < 4; q++){
                    const __nv_bfloat16* wp = wc + (size_t)(warp*16 + g*4 + q)*512 + lane*16;
                    uint4 u0 = *(const uint4*)wp;
                    uint4 u1 = *(const uint4*)(wp + 8);
                    sums[q] = dot16(u0, u1, rreg);
                }
#pragma unroll
                for (int q = 0; q < 4; q++) sums[q] = warp_sum(sums[q]);
                if (lane < 4){
                    float v = (lane==0)?sums[0]:(lane==1)?sums[1]:(lane==2)?sums[2]:sums[3];
                    int row = warp*16 + g*4 + lane;
                    v += s_pb[row];
                    if (warp < 8) s_add[row]       = v + qv[g];
                    else          s_trr[row - 128] = tanh_mufu(v);
                }
            }
        } else {
#pragma unroll
            for (int g = 0; g < 4; g++){
                uint4 u[4][2];
#pragma unroll
                for (int q = 0; q < 4; q++){
                    const __nv_bfloat16* wp = grr + (size_t)(warp*16 + g*4 + q - 128)*512 + lane*16;
                    u[q][0] = *(const uint4*)wp;
                    u[q][1] = *(const uint4*)(wp + 8);
                }
                float sums[4];
#pragma unroll
                for (int q = 0; q < 4; q++) sums[q] = dot16(u[q][0], u[q][1], rreg);
#pragma unroll
                for (int q = 0; q < 4; q++) sums[q] = warp_sum(sums[q]);
                if (lane < 4){
                    float v = (lane==0)?sums[0]:(lane==1)?sums[1]:(lane==2)?sums[2]:sums[3];
                    int row = warp*16 + g*4 + lane;
                    s_trr[row - 128] = tanh_mufu(v + s_pb[row]);
                }
            }
        }
        __syncthreads();

        {
            float areg[4], mreg[4];
#pragma unroll
            for (int i = 0; i < 4; i++){
                areg[i] = s_add[lane*4 + i];
                mreg[i] = s_mw[lane*4 + i];
            }
#pragma unroll
            for (int g = 0; g < 4; g++){
                int s0 = warp*16 + g*4;
                float a4[4];
#pragma unroll
                for (int q = 0; q < 4; q++){
                    const __nv_bfloat16* cd = g_codm + (size_t)(b*256 + s0 + q)*512
                                            + rank*128 + lane*4;
                    uint2 u = *(const uint2*)cd;
                    float2 c01 = __bfloat1622float2(*(const __nv_bfloat162*)&u.x);
                    float2 c23 = __bfloat1622float2(*(const __nv_bfloat162*)&u.y);
                    a4[q] = tanh_mufu(c01.x + areg[0]) * mreg[0]
                          + tanh_mufu(c01.y + areg[1]) * mreg[1]
                          + tanh_mufu(c23.x + areg[2]) * mreg[2]
                          + tanh_mufu(c23.y + areg[3]) * mreg[3];
                }
#pragma unroll
                for (int q = 0; q < 4; q++) a4[q] = warp_sum(a4[q]);
                if (lane < 4){
                    float v = (lane==0)?a4[0]:(lane==1)?a4[1]:(lane==2)?a4[2]:a4[3];
                    s_lp[s0 + lane] = v;
                }
            }
        }
        CLUSTER_SYNC();

        if (tid < 256){
            unsigned int sa = s2u(&s_lp[tid]);
            float v = s_lp[tid] + msb0
                    + dsmem_ld(sa, (rank+1)&3u)
                    + dsmem_ld(sa, (rank+2)&3u)
                    + dsmem_ld(sa, (rank+3)&3u);
            s_lgf[tid] = v;
        }
        __syncthreads();

        {
            float l = s_lgf[tid & 255];
            float m = l;
#pragma unroll
            for (int o = 16; o; o >>= 1) m = fmaxf(m, __shfl_xor_sync(0xffffffffu, m, o));
            if (lane == 0) s_red[warp] = m;
            __syncthreads();
            float mx = s_red[0];
#pragma unroll
            for (int i = 1; i < 16; i++) mx = fmaxf(mx, s_red[i]);
            float ex = __expf(l - mx);
            float smm = warp_sum(ex);
            if (lane == 0) s_red[16 + warp] = smm;
            __syncthreads();
            float tot = s_red[16];
#pragma unroll
            for (int i = 17; i < 32; i++) tot += s_red[i];
            tot *= 0.5f;
            s_sw[tid & 255] = ex * (1.0f / tot);
        }
        __syncthreads();

        {
            int e  = (int)rank*128 + (tid & 127);
            int sq = tid >> 7;
            const float* cb = g_co + (size_t)(b*256 + sq*64)*512 + e;
            const float* wv = s_sw + sq*64;
            float acc = 0.f;
#pragma unroll 16
            for (int s = 0; s < 64; s++)
                acc = fmaf(wv[s], cb[(size_t)s*512], acc);
            s_pt[tid] = acc;
            __syncthreads();
            if (tid < 128){
                float v = s_pt[tid] + s_pt[tid+128] + s_pt[tid+256] + s_pt[tid+384]
                        + s_trr[tid];
                s_rn[tid] = v;
                if (t == TT-1) g_r[b*512 + (int)rank*128 + tid] = v;
            }
        }
        CLUSTER_SYNC();

        if (t < TT-1){
            s_r[tid] = dsmem_ld(s2u(&s_rn[tid & 127]), (unsigned int)(tid >> 7));
            __syncthreads();
        }
    }

    CLUSTER_SYNC();
}

// ---------------- final: g = rg(r) + qg(qh) ----------------
__global__ __launch_bounds__(256) void final_g(const float* __restrict__ rg_w,
                                               const float* __restrict__ rg_b,
                                               const float* __restrict__ qg_w,
                                               const float* __restrict__ qg_b,
                                               const float* __restrict__ qh,
                                               float* __restrict__ out)
{
    __shared__ __align__(16) float sr[512];
    __shared__ __align__(16) float sq[512];
    int bx  = blockIdx.x;
    int b   = bx >> 6, ec = bx & 63;
    int tid = threadIdx.x, lane = tid & 31, warp = tid >> 5;
    sr[tid]       = g_r[b*512 + tid];
    sr[tid + 256] = g_r[b*512 + tid + 256];
    sq[tid]       = qh[b*512 + tid];
    sq[tid + 256] = qh[b*512 + tid + 256];
    __syncthreads();
    int e = ec*8 + warp;
    const float* w1 = rg_w + e*512;
    const float* w2 = qg_w + e*512;
    float s = 0.f;
#pragma unroll
    for (int i = 0; i < 4; i++){
        int k = i*128 + lane*4;
        float4 a = *(const float4*)(w1 + k); float4 x = *(const float4*)(sr + k);
        float4 c = *(const float4*)(w2 + k); float4 y = *(const float4*)(sq + k);
        s += a.x*x.x + a.y*x.y + a.z*x.z + a.w*x.w;
        s += c.x*y.x + c.y*y.y + c.z*y.z + c.w*y.w;
    }
    s = warp_sum(s);
    if (lane == 0) out[b*512 + e] = s + rg_b[e] + qg_b[e];
}

// ---------------- host launch ----------------
extern "C" void kernel_launch(void* const* d_in, const int* in_sizes, int n_in,
                              void* d_out, int out_size)
{
    const float* ctx  = (const float*)d_in[0];
    const float* qout = (const float*)d_in[2];
    const float* qh   = (const float*)d_in[3];
    const float* img  = (const float*)d_in[4];
    const float* fc1w = (const float*)d_in[6];  const float* fc1b = (const float*)d_in[7];
    const float* fc2w = (const float*)d_in[8];  const float* fc2b = (const float*)d_in[9];
    const float* dmw  = (const float*)d_in[10]; const float* dmb  = (const float*)d_in[11];
    const float* msw  = (const float*)d_in[12]; const float* msb  = (const float*)d_in[13];
    const float* rmw  = (const float*)d_in[14]; const float* rmb  = (const float*)d_in[15];
    const float* qmw  = (const float*)d_in[16]; const float* qmb  = (const float*)d_in[17];
    const float* rrw  = (const float*)d_in[18]; const float* rrb  = (const float*)d_in[19];
    const float* rgw  = (const float*)d_in[20]; const float* rgb  = (const float*)d_in[21];
    const float* qgw  = (const float*)d_in[22]; const float* qgb  = (const float*)d_in[23];

    cudaFuncSetAttribute(scan_cluster, cudaFuncAttributeMaxDynamicSharedMemorySize,
                         SMEM_SCAN_BYTES);
    cudaFuncSetAttribute(codm_mma, cudaFuncAttributeMaxDynamicSharedMemorySize,
                         CODM_SMEM_BYTES);

    prep_all<<<768, 256>>>(fc1b, fc2b, rmw, rrw, dmw);

    // co (fused perm+concat GEMM, pipelined, + bf16 hi/lo split) + qm GEMM in ONE launch
    gemm_A<<<352, 256>>>(ctx, img, fc1w, fc2w, qout, qmw, qmb);

    // codm = co @ dm_w^T + dm_b via split-bf16 HMMA (3-term, ~fp32 precision)
    codm_mma<<<256, 256, CODM_SMEM_BYTES>>>(dmb);

    // ENTIRE scan: 32 independent 4-CTA clusters, 2 cluster syncs/step
    scan_cluster<<<128, 512, SMEM_SCAN_BYTES>>>(rmb, rrb, msw, msb);

    final_g<<<2048, 256>>>(rgw, rgb, qgw, qgb, qh, (float*)d_out);
}

// round 15
// speedup vs baseline: 1.1461x; 1.1213x over previous
#include <cuda_runtime.h>
#include <cuda_bf16.h>
#include <cstdint>
#include <math.h>

#define DD 512
#define SS 256
#define BB 32
#define TT 24
#define NROWS (BB*SS)   // 8192

#define CROWS 208
// dynamic smem layout (float offsets) — scan kernel
#define OFF_WC   0
#define OFF_R    (CROWS*256)
#define OFF_ADD  (OFF_R + 512)
#define OFF_TRR  (OFF_ADD + 128)
#define OFF_LP   (OFF_TRR + 128)
#define OFF_LGF  (OFF_LP + 256)
#define OFF_RED  (OFF_LGF + 256)
#define OFF_SW   (OFF_RED + 32)
#define OFF_PT   (OFF_SW + 256)
#define OFF_RN   (OFF_PT + 512)
#define OFF_MW   (OFF_RN + 128)
#define OFF_PB   (OFF_MW + 128)
#define SMEM_SCAN_FLOATS (OFF_PB + 256)
#define SMEM_SCAN_BYTES  (SMEM_SCAN_FLOATS*4)

#define MPAD 72
#define CODM_SMEM_BYTES (4*128*MPAD*2)   // Ah,Al,Bh,Bl tiles = 73728 B

// ---------------- device scratch ----------------
__device__ float g_co[NROWS*512];
__device__ __nv_bfloat16 g_cohi[NROWS*512];
__device__ __nv_bfloat16 g_colo[NROWS*512];
__device__ __nv_bfloat16 g_codm[NROWS*512];
__device__ float g_qm[TT*BB*512];
__device__ __nv_bfloat16 g_wbf[1024*512];          // [rm_w | rr_w] bf16 (scan)
__device__ __nv_bfloat16 g_dmhi[512*512];
__device__ __nv_bfloat16 g_dmlo[512*512];

// ---------------- helpers ----------------
__device__ __forceinline__ float tanh_mufu(float x){
    float y;
    asm("tanh.approx.f32 %0, %1;" : "=f"(y) : "f"(x));
    return y;
}

__device__ __forceinline__ float warp_sum(float v){
#pragma unroll
    for (int o = 16; o; o >>= 1) v += __shfl_xor_sync(0xffffffffu, v, o);
    return v;
}

__device__ __forceinline__ unsigned int s2u(const void* p){
    unsigned int a;
    asm("{ .reg .u64 t; cvta.to.shared.u64 t, %1; cvt.u32.u64 %0, t; }" : "=r"(a) : "l"(p));
    return a;
}

__device__ __forceinline__ float dsmem_ld(unsigned int saddr, unsigned int rank){
    unsigned int ra; float v;
    asm volatile("mapa.shared::cluster.u32 %0, %1, %2;" : "=r"(ra) : "r"(saddr), "r"(rank));
    asm volatile("ld.shared::cluster.f32 %0, [%1];" : "=f"(v) : "r"(ra) : "memory");
    return v;
}

#define CLUSTER_SYNC() do{ \
    asm volatile("barrier.cluster.arrive.aligned;" ::: "memory"); \
    asm volatile("barrier.cluster.wait.aligned;"   ::: "memory"); }while(0)

__device__ __forceinline__ void cpa16(unsigned int s, const void* g){
    asm volatile("cp.async.cg.shared.global [%0], [%1], 16;" :: "r"(s), "l"(g));
}
#define CPA_WAIT() asm volatile("cp.async.commit_group;\n\tcp.async.wait_group 0;" ::: "memory")

// dot of 16 bf16 weights with 16 fp32 r values
__device__ __forceinline__ float dot16(uint4 u0, uint4 u1, const float* r){
    float s = 0.f; float2 c;
    c = __bfloat1622float2(*(const __nv_bfloat162*)&u0.x); s += c.x*r[0]  + c.y*r[1];
    c = __bfloat1622float2(*(const __nv_bfloat162*)&u0.y); s += c.x*r[2]  + c.y*r[3];
    c = __bfloat1622float2(*(const __nv_bfloat162*)&u0.z); s += c.x*r[4]  + c.y*r[5];
    c = __bfloat1622float2(*(const __nv_bfloat162*)&u0.w); s += c.x*r[6]  + c.y*r[7];
    c = __bfloat1622float2(*(const __nv_bfloat162*)&u1.x); s += c.x*r[8]  + c.y*r[9];
    c = __bfloat1622float2(*(const __nv_bfloat162*)&u1.y); s += c.x*r[10] + c.y*r[11];
    c = __bfloat1622float2(*(const __nv_bfloat162*)&u1.z); s += c.x*r[12] + c.y*r[13];
    c = __bfloat1622float2(*(const __nv_bfloat162*)&u1.w); s += c.x*r[14] + c.y*r[15];
    return s;
}

// ---------------- GEMM building blocks ----------------
__device__ __forceinline__ void sts16(float* As, float* Bs, int lr0, int lc4,
                                      float4 a0, float4 a1, float4 w0, float4 w1){
    As[(lc4+0)*132 + lr0]      = a0.x; As[(lc4+1)*132 + lr0]      = a0.y;
    As[(lc4+2)*132 + lr0]      = a0.z; As[(lc4+3)*132 + lr0]      = a0.w;
    As[(lc4+0)*132 + lr0 + 64] = a1.x; As[(lc4+1)*132 + lr0 + 64] = a1.y;
    As[(lc4+2)*132 + lr0 + 64] = a1.z; As[(lc4+3)*132 + lr0 + 64] = a1.w;
    Bs[(lc4+0)*132 + lr0]      = w0.x; Bs[(lc4+1)*132 + lr0]      = w0.y;
    Bs[(lc4+2)*132 + lr0]      = w0.z; Bs[(lc4+3)*132 + lr0]      = w0.w;
    Bs[(lc4+0)*132 + lr0 + 64] = w1.x; Bs[(lc4+1)*132 + lr0 + 64] = w1.y;
    Bs[(lc4+2)*132 + lr0 + 64] = w1.z; Bs[(lc4+3)*132 + lr0 + 64] = w1.w;
}

__device__ __forceinline__ void mm16(const float* As, const float* Bs,
                                     float acc[8][8], int tx, int ty){
#pragma unroll
    for (int k = 0; k < 16; k++){
        float4 af0 = *(const float4*)&As[k*132 + ty*8];
        float4 af1 = *(const float4*)&As[k*132 + ty*8 + 4];
        float4 bf0 = *(const float4*)&Bs[k*132 + tx*8];
        float4 bf1 = *(const float4*)&Bs[k*132 + tx*8 + 4];
        float av[8] = {af0.x,af0.y,af0.z,af0.w,af1.x,af1.y,af1.z,af1.w};
        float bv[8] = {bf0.x,bf0.y,bf0.z,bf0.w,bf1.x,bf1.y,bf1.z,bf1.w};
#pragma unroll
        for (int i = 0; i < 8; i++)
#pragma unroll
            for (int j = 0; j < 8; j++)
                acc[i][j] = fmaf(av[i], bv[j], acc[i][j]);
    }
}

// ---------------- MEGA launch A: co GEMM + qm GEMM + weight conversions ----------------
// blocks [0,256):    co = perm(ctx)@fc1^T + perm(img)@fc2^T + (fc1b+fc2b); fp32 + hi/lo bf16
// blocks [256,352):  qm = qout@qm_w^T + qm_b
// blocks [352,1120): conversions: rm/rr -> g_wbf bf16; dm -> hi/lo bf16
__global__ __launch_bounds__(256) void gemm_A(const float* __restrict__ ctx,
                                              const float* __restrict__ img,
                                              const float* __restrict__ fc1w,
                                              const float* __restrict__ fc1b,
                                              const float* __restrict__ fc2w,
                                              const float* __restrict__ fc2b,
                                              const float* __restrict__ qout,
                                              const float* __restrict__ qmw,
                                              const float* __restrict__ qmb,
                                              const float* __restrict__ rm_w,
                                              const float* __restrict__ rr_w,
                                              const float* __restrict__ dm_w)
{
    __shared__ __align__(16) float sh[4*2112];
    const int bid = blockIdx.x;
    const int tid = threadIdx.x;

    if (bid < 256){
        const int m0  = (bid >> 2) * 128;
        const int n0  = (bid & 3) * 128;
        const int tx  = tid & 15, ty = tid >> 4;
        const int lr0 = tid >> 2;
        const int lc4 = (tid & 3) * 4;

        const int r1 = m0 + lr0, r2 = r1 + 64;
        const int p1 = (r1 & 255)*32 + (r1 >> 8);
        const int p2 = (r2 & 255)*32 + (r2 >> 8);

        const float* A1h[2] = { ctx + (size_t)p1*512 + lc4,  img + (size_t)p1*512 + lc4 };
        const float* A2h[2] = { ctx + (size_t)p2*512 + lc4,  img + (size_t)p2*512 + lc4 };
        const float* W1h[2] = { fc1w + (size_t)(n0+lr0)*512 + lc4,
                                fc2w + (size_t)(n0+lr0)*512 + lc4 };
        const float* W2h[2] = { fc1w + (size_t)(n0+lr0+64)*512 + lc4,
                                fc2w + (size_t)(n0+lr0+64)*512 + lc4 };

        float acc[8][8] = {};
        float4 a0, a1, w0, w1;

        a0 = *(const float4*)A1h[0]; a1 = *(const float4*)A2h[0];
        w0 = *(const float4*)W1h[0]; w1 = *(const float4*)W2h[0];
        sts16(sh, sh + 2112, lr0, lc4, a0, a1, w0, w1);
        __syncthreads();

#pragma unroll 1
        for (int it = 0; it < 64; it++){
            const bool has = (it + 1 < 64);
            if (has){
                const int h  = (it+1) >> 5;
                const int kt = ((it+1) & 31) * 16;
                a0 = *(const float4*)((h ? A1h[1] : A1h[0]) + kt);
                a1 = *(const float4*)((h ? A2h[1] : A2h[0]) + kt);
                w0 = *(const float4*)((h ? W1h[1] : W1h[0]) + kt);
                w1 = *(const float4*)((h ? W2h[1] : W2h[0]) + kt);
            }
            const int cur = (it & 1) * 4224;
            mm16(sh + cur, sh + cur + 2112, acc, tx, ty);
            if (has){
                const int nxt = ((it+1) & 1) * 4224;
                sts16(sh + nxt, sh + nxt + 2112, lr0, lc4, a0, a1, w0, w1);
            }
            __syncthreads();
        }

        float bj[8];
#pragma unroll
        for (int j = 0; j < 8; j++){
            int n = n0 + tx*8 + j;
            bj[j] = fc1b[n] + fc2b[n];
        }
#pragma unroll
        for (int i = 0; i < 8; i++){
            int m = m0 + ty*8 + i;
            float vals[8];
#pragma unroll
            for (int j = 0; j < 8; j++) vals[j] = acc[i][j] + bj[j];
            *(float4*)&g_co[(size_t)m*512 + n0 + tx*8]     = make_float4(vals[0],vals[1],vals[2],vals[3]);
            *(float4*)&g_co[(size_t)m*512 + n0 + tx*8 + 4] = make_float4(vals[4],vals[5],vals[6],vals[7]);
            __nv_bfloat16 h[8], l[8];
#pragma unroll
            for (int j = 0; j < 8; j++){
                h[j] = __float2bfloat16(vals[j]);
                l[j] = __float2bfloat16(vals[j] - __bfloat162float(h[j]));
            }
            *(uint4*)&g_cohi[(size_t)m*512 + n0 + tx*8] = *(uint4*)h;
            *(uint4*)&g_colo[(size_t)m*512 + n0 + tx*8] = *(uint4*)l;
        }
    } else if (bid < 352){
        float* As = sh;            // stride 68
        float* Bs = sh + 16*68;
        const int qid = bid - 256;
        const int m0  = (qid >> 3) * 64;
        const int n0  = (qid & 7) * 64;
        const int tx  = tid & 15, ty = tid >> 4;
        const int lr0 = tid >> 2;
        const int lc4 = (tid & 3) * 4;

        float acc[4][4] = {};
        const float* A1 = qout + (size_t)(m0 + lr0)*512 + lc4;
        const float* W1 = qmw  + (size_t)(n0 + lr0)*512 + lc4;

        for (int kt = 0; kt < 512; kt += 16){
            float4 a0 = *(const float4*)(A1 + kt);
            float4 w0 = *(const float4*)(W1 + kt);
            __syncthreads();
            As[(lc4+0)*68 + lr0] = a0.x; As[(lc4+1)*68 + lr0] = a0.y;
            As[(lc4+2)*68 + lr0] = a0.z; As[(lc4+3)*68 + lr0] = a0.w;
            Bs[(lc4+0)*68 + lr0] = w0.x; Bs[(lc4+1)*68 + lr0] = w0.y;
            Bs[(lc4+2)*68 + lr0] = w0.z; Bs[(lc4+3)*68 + lr0] = w0.w;
            __syncthreads();
#pragma unroll
            for (int k = 0; k < 16; k++){
                float4 av = *(const float4*)&As[k*68 + ty*4];
                float4 bv = *(const float4*)&Bs[k*68 + tx*4];
                float aa[4] = {av.x,av.y,av.z,av.w};
                float bb[4] = {bv.x,bv.y,bv.z,bv.w};
#pragma unroll
                for (int i = 0; i < 4; i++)
#pragma unroll
                    for (int j = 0; j < 4; j++)
                        acc[i][j] = fmaf(aa[i], bb[j], acc[i][j]);
            }
        }

        float4 bq = *(const float4*)&qmb[n0 + tx*4];
        float bj[4] = {bq.x,bq.y,bq.z,bq.w};
#pragma unroll
        for (int i = 0; i < 4; i++){
            int m = m0 + ty*4 + i;
            float4 o = make_float4(acc[i][0]+bj[0], acc[i][1]+bj[1],
                                   acc[i][2]+bj[2], acc[i][3]+bj[3]);
            *(float4*)&g_qm[(size_t)m*512 + n0 + tx*4] = o;
        }
    } else {
        // conversions (same ordering as old prep_all, minus bcat)
        int v = (bid - 352) * 256 + tid;       // 0..196607
        if (v < 131072){
            const float* src = (v < 65536) ? rm_w : rr_w;
            __nv_bfloat16* dst = (v < 65536) ? g_wbf : (g_wbf + (size_t)512*512);
            int i = v & 65535;
            float4 f = ((const float4*)src)[i];
            __nv_bfloat162 p0 = __floats2bfloat162_rn(f.x, f.y);
            __nv_bfloat162 p1 = __floats2bfloat162_rn(f.z, f.w);
            ((uint2*)dst)[i] = make_uint2(*(unsigned*)&p0, *(unsigned*)&p1);
        } else {
            int i = v - 131072;
            float4 f = ((const float4*)dm_w)[i];
            float fv[4] = {f.x, f.y, f.z, f.w};
            __nv_bfloat16 h[4], l[4];
#pragma unroll
            for (int j = 0; j < 4; j++){
                h[j] = __float2bfloat16(fv[j]);
                l[j] = __float2bfloat16(fv[j] - __bfloat162float(h[j]));
            }
            ((uint2*)g_dmhi)[i] = *(uint2*)h;
            ((uint2*)g_dmlo)[i] = *(uint2*)l;
        }
    }
}

// ---------------- codm via split-bf16 mma.sync (cp.async staging) ----------------
__global__ __launch_bounds__(256) void codm_mma(const float* __restrict__ bias)
{
    extern __shared__ __nv_bfloat16 smb[];
    __nv_bfloat16* sAh = smb;
    __nv_bfloat16* sAl = smb + 128*MPAD;
    __nv_bfloat16* sBh = smb + 2*128*MPAD;
    __nv_bfloat16* sBl = smb + 3*128*MPAD;

    const int tid  = threadIdx.x;
    const int warp = tid >> 5, lane = tid & 31;
    const int m0 = (int)(blockIdx.x >> 2) * 128;
    const int n0 = (int)(blockIdx.x & 3) * 128;
    const int wr = warp >> 1;
    const int wc = warp & 1;

    float acc[2][8][4];
#pragma unroll
    for (int i = 0; i < 2; i++)
#pragma unroll
        for (int j = 0; j < 8; j++)
#pragma unroll
            for (int k = 0; k < 4; k++) acc[i][j][k] = 0.f;

    const int ldrow = lane & 15;
    const int ldcol = (lane >> 4) * 8;

#pragma unroll 1
    for (int kc = 0; kc < 8; kc++){
#pragma unroll
        for (int t = 0; t < 4; t++){
            int i = tid + t*256;
            int r = i >> 3, c = (i & 7) * 8;
            size_t ga = (size_t)(m0 + r)*512 + kc*64 + c;
            size_t gb = (size_t)(n0 + r)*512 + kc*64 + c;
            unsigned so = (unsigned)((r*MPAD + c) * 2);
            cpa16(s2u(sAh) + so, &g_cohi[ga]);
            cpa16(s2u(sAl) + so, &g_colo[ga]);
            cpa16(s2u(sBh) + so, &g_dmhi[gb]);
            cpa16(s2u(sBl) + so, &g_dmlo[gb]);
        }
        CPA_WAIT();
        __syncthreads();

#pragma unroll
        for (int ks = 0; ks < 4; ks++){
            unsigned int ah[2][4], al[2][4];
#pragma unroll
            for (int mt = 0; mt < 2; mt++){
                unsigned int adh = s2u(&sAh[(wr*32 + mt*16 + ldrow)*MPAD + ks*16 + ldcol]);
                asm volatile("ldmatrix.sync.aligned.m8n8.x4.shared.b16 {%0,%1,%2,%3}, [%4];"
                             : "=r"(ah[mt][0]), "=r"(ah[mt][1]), "=r"(ah[mt][2]), "=r"(ah[mt][3])
                             : "r"(adh));
                unsigned int adl = s2u(&sAl[(wr*32 + mt*16 + ldrow)*MPAD + ks*16 + ldcol]);
                asm volatile("ldmatrix.sync.aligned.m8n8.x4.shared.b16 {%0,%1,%2,%3}, [%4];"
                             : "=r"(al[mt][0]), "=r"(al[mt][1]), "=r"(al[mt][2]), "=r"(al[mt][3])
                             : "r"(adl));
            }
            unsigned int bfr[8][2];
#pragma unroll
            for (int nb = 0; nb < 4; nb++){
                unsigned int bd = s2u(&sBh[(wc*64 + nb*16 + ldrow)*MPAD + ks*16 + ldcol]);
                unsigned int r0, r1, r2, r3;
                asm volatile("ldmatrix.sync.aligned.m8n8.x4.shared.b16 {%0,%1,%2,%3}, [%4];"
                             : "=r"(r0), "=r"(r1), "=r"(r2), "=r"(r3) : "r"(bd));
                bfr[nb*2][0]   = r0; bfr[nb*2][1]   = r2;
                bfr[nb*2+1][0] = r1; bfr[nb*2+1][1] = r3;
            }
#pragma unroll
            for (int mt = 0; mt < 2; mt++)
#pragma unroll
                for (int nt = 0; nt < 8; nt++){
                    asm volatile(
                        "mma.sync.aligned.m16n8k16.row.col.f32.bf16.bf16.f32 "
                        "{%0,%1,%2,%3}, {%4,%5,%6,%7}, {%8,%9}, {%0,%1,%2,%3};"
                        : "+f"(acc[mt][nt][0]), "+f"(acc[mt][nt][1]),
                          "+f"(acc[mt][nt][2]), "+f"(acc[mt][nt][3])
                        : "r"(ah[mt][0]), "r"(ah[mt][1]), "r"(ah[mt][2]), "r"(ah[mt][3]),
                          "r"(bfr[nt][0]), "r"(bfr[nt][1]));
                    asm volatile(
                        "mma.sync.aligned.m16n8k16.row.col.f32.bf16.bf16.f32 "
                        "{%0,%1,%2,%3}, {%4,%5,%6,%7}, {%8,%9}, {%0,%1,%2,%3};"
                        : "+f"(acc[mt][nt][0]), "+f"(acc[mt][nt][1]),
                          "+f"(acc[mt][nt][2]), "+f"(acc[mt][nt][3])
                        : "r"(al[mt][0]), "r"(al[mt][1]), "r"(al[mt][2]), "r"(al[mt][3]),
                          "r"(bfr[nt][0]), "r"(bfr[nt][1]));
                }
#pragma unroll
            for (int nb = 0; nb < 4; nb++){
                unsigned int bd = s2u(&sBl[(wc*64 + nb*16 + ldrow)*MPAD + ks*16 + ldcol]);
                unsigned int r0, r1, r2, r3;
                asm volatile("ldmatrix.sync.aligned.m8n8.x4.shared.b16 {%0,%1,%2,%3}, [%4];"
                             : "=r"(r0), "=r"(r1), "=r"(r2), "=r"(r3) : "r"(bd));
                bfr[nb*2][0]   = r0; bfr[nb*2][1]   = r2;
                bfr[nb*2+1][0] = r1; bfr[nb*2+1][1] = r3;
            }
#pragma unroll
            for (int mt = 0; mt < 2; mt++)
#pragma unroll
                for (int nt = 0; nt < 8; nt++){
                    asm volatile(
                        "mma.sync.aligned.m16n8k16.row.col.f32.bf16.bf16.f32 "
                        "{%0,%1,%2,%3}, {%4,%5,%6,%7}, {%8,%9}, {%0,%1,%2,%3};"
                        : "+f"(acc[mt][nt][0]), "+f"(acc[mt][nt][1]),
                          "+f"(acc[mt][nt][2]), "+f"(acc[mt][nt][3])
                        : "r"(ah[mt][0]), "r"(ah[mt][1]), "r"(ah[mt][2]), "r"(ah[mt][3]),
                          "r"(bfr[nt][0]), "r"(bfr[nt][1]));
                }
        }
        __syncthreads();
    }

    const int g  = lane >> 2;
    const int cc = (lane & 3) * 2;
#pragma unroll
    for (int mt = 0; mt < 2; mt++){
#pragma unroll
        for (int nt = 0; nt < 8; nt++){
            int n = n0 + wc*64 + nt*8 + cc;
            float b0 = bias[n], b1 = bias[n+1];
            int r0 = m0 + wr*32 + mt*16 + g;
            __nv_bfloat162 p0 = __floats2bfloat162_rn(acc[mt][nt][0] + b0,
                                                      acc[mt][nt][1] + b1);
            *(__nv_bfloat162*)&g_codm[(size_t)r0*512 + n] = p0;
            __nv_bfloat162 p1 = __floats2bfloat162_rn(acc[mt][nt][2] + b0,
                                                      acc[mt][nt][3] + b1);
            *(__nv_bfloat162*)&g_codm[(size_t)(r0+8)*512 + n] = p1;
        }
    }
}

// ---------------- persistent cluster scan (+ merged final_g epilogue) ----------------
__global__ void __launch_bounds__(512, 1) __cluster_dims__(4, 1, 1)
scan_cluster(const float* __restrict__ rm_b, const float* __restrict__ rr_b,
             const float* __restrict__ ms_w, const float* __restrict__ ms_b,
             const float* __restrict__ rg_w, const float* __restrict__ rg_b,
             const float* __restrict__ qg_w, const float* __restrict__ qg_b,
             const float* __restrict__ qh,   float* __restrict__ out)
{
    extern __shared__ float sm[];
    __nv_bfloat16* wc = (__nv_bfloat16*)(sm + OFF_WC);
    float* s_r   = sm + OFF_R;
    float* s_add = sm + OFF_ADD;
    float* s_trr = sm + OFF_TRR;
    float* s_lp  = sm + OFF_LP;
    float* s_lgf = sm + OFF_LGF;
    float* s_red = sm + OFF_RED;
    float* s_sw  = sm + OFF_SW;
    float* s_pt  = sm + OFF_PT;
    float* s_rn  = sm + OFF_RN;
    float* s_mw  = sm + OFF_MW;
    float* s_pb  = sm + OFF_PB;

    const int tid = threadIdx.x, lane = tid & 31, warp = tid >> 5;
    unsigned int rank; asm("mov.u32 %0, %%cluster_ctarank;" : "=r"(rank));
    const int b = blockIdx.x >> 2;

    const __nv_bfloat16* grm = g_wbf + (size_t)(rank*128)*512;
    const __nv_bfloat16* grr = g_wbf + (size_t)(512 + rank*128)*512;

    for (int idx = tid; idx < CROWS*64; idx += 512){
        int row = idx >> 6, c = idx & 63;
        const __nv_bfloat16* src = (row < 128) ? (grm + (size_t)row*512)
                                               : (grr + (size_t)(row-128)*512);
        ((uint4*)wc)[idx] = ((const uint4*)src)[c];
    }
    if (tid < 256) s_pb[tid] = (tid < 128) ? rm_b[rank*128 + tid]
                                           : rr_b[rank*128 + tid - 128];
    if (tid < 128) s_mw[tid] = ms_w[rank*128 + tid];
    s_r[tid] = 0.f;
    const float msb0 = ms_b[0];
    __syncthreads();

    for (int t = 0; t < TT; t++){
        float rreg[16];
#pragma unroll
        for (int i = 0; i < 4; i++)
            ((float4*)rreg)[i] = *(const float4*)&s_r[lane*16 + i*4];

        float qv[4] = {0.f,0.f,0.f,0.f};
        if (warp < 8 && lane < 4){
#pragma unroll
            for (int g = 0; g < 4; g++)
                qv[g] = g_qm[(size_t)(t*BB + b)*512 + rank*128 + warp*16 + g*4 + lane];
        }

        if (warp < 13){
#pragma unroll
            for (int g = 0; g < 4; g++){
                float sums[4];
#pragma unroll
                for (int q = 0; q < 4; q++){
                    const __nv_bfloat16* wp = wc + (size_t)(warp*16 + g*4 + q)*512 + lane*16;
                    uint4 u0 = *(const uint4*)wp;
                    uint4 u1 = *(const uint4*)(wp + 8);
                    sums[q] = dot16(u0, u1, rreg);
                }
#pragma unroll
                for (int q = 0; q < 4; q++) sums[q] = warp_sum(sums[q]);
                if (lane < 4){
                    float v = (lane==0)?sums[0]:(lane==1)?sums[1]:(lane==2)?sums[2]:sums[3];
                    int row = warp*16 + g*4 + lane;
                    v += s_pb[row];
                    if (warp < 8) s_add[row]       = v + qv[g];
                    else          s_trr[row - 128] = tanh_mufu(v);
                }
            }
        } else {
#pragma unroll
            for (int g = 0; g < 4; g++){
                uint4 u[4][2];
#pragma unroll
                for (int q = 0; q < 4; q++){
                    const __nv_bfloat16* wp = grr + (size_t)(warp*16 + g*4 + q - 128)*512 + lane*16;
                    u[q][0] = *(const uint4*)wp;
                    u[q][1] = *(const uint4*)(wp + 8);
                }
                float sums[4];
#pragma unroll
                for (int q = 0; q < 4; q++) sums[q] = dot16(u[q][0], u[q][1], rreg);
#pragma unroll
                for (int q = 0; q < 4; q++) sums[q] = warp_sum(sums[q]);
                if (lane < 4){
                    float v = (lane==0)?sums[0]:(lane==1)?sums[1]:(lane==2)?sums[2]:sums[3];
                    int row = warp*16 + g*4 + lane;
                    s_trr[row - 128] = tanh_mufu(v + s_pb[row]);
                }
            }
        }
        __syncthreads();

        {
            float areg[4], mreg[4];
#pragma unroll
            for (int i = 0; i < 4; i++){
                areg[i] = s_add[lane*4 + i];
                mreg[i] = s_mw[lane*4 + i];
            }
#pragma unroll
            for (int g = 0; g < 4; g++){
                int s0 = warp*16 + g*4;
                float a4[4];
#pragma unroll
                for (int q = 0; q < 4; q++){
                    const __nv_bfloat16* cd = g_codm + (size_t)(b*256 + s0 + q)*512
                                            + rank*128 + lane*4;
                    uint2 u = *(const uint2*)cd;
                    float2 c01 = __bfloat1622float2(*(const __nv_bfloat162*)&u.x);
                    float2 c23 = __bfloat1622float2(*(const __nv_bfloat162*)&u.y);
                    a4[q] = tanh_mufu(c01.x + areg[0]) * mreg[0]
                          + tanh_mufu(c01.y + areg[1]) * mreg[1]
                          + tanh_mufu(c23.x + areg[2]) * mreg[2]
                          + tanh_mufu(c23.y + areg[3]) * mreg[3];
                }
#pragma unroll
                for (int q = 0; q < 4; q++) a4[q] = warp_sum(a4[q]);
                if (lane < 4){
                    float v = (lane==0)?a4[0]:(lane==1)?a4[1]:(lane==2)?a4[2]:a4[3];
                    s_lp[s0 + lane] = v;
                }
            }
        }
        CLUSTER_SYNC();

        if (tid < 256){
            unsigned int sa = s2u(&s_lp[tid]);
            float v = s_lp[tid] + msb0
                    + dsmem_ld(sa, (rank+1)&3u)
                    + dsmem_ld(sa, (rank+2)&3u)
                    + dsmem_ld(sa, (rank+3)&3u);
            s_lgf[tid] = v;
        }
        __syncthreads();

        {
            float l = s_lgf[tid & 255];
            float m = l;
#pragma unroll
            for (int o = 16; o; o >>= 1) m = fmaxf(m, __shfl_xor_sync(0xffffffffu, m, o));
            if (lane == 0) s_red[warp] = m;
            __syncthreads();
            float mx = s_red[0];
#pragma unroll
            for (int i = 1; i < 16; i++) mx = fmaxf(mx, s_red[i]);
            float ex = __expf(l - mx);
            float smm = warp_sum(ex);
            if (lane == 0) s_red[16 + warp] = smm;
            __syncthreads();
            float tot = s_red[16];
#pragma unroll
            for (int i = 17; i < 32; i++) tot += s_red[i];
            tot *= 0.5f;
            s_sw[tid & 255] = ex * (1.0f / tot);
        }
        __syncthreads();

        {
            int e  = (int)rank*128 + (tid & 127);
            int sq = tid >> 7;
            const float* cb = g_co + (size_t)(b*256 + sq*64)*512 + e;
            const float* wv = s_sw + sq*64;
            float acc = 0.f;
#pragma unroll 16
            for (int s = 0; s < 64; s++)
                acc = fmaf(wv[s], cb[(size_t)s*512], acc);
            s_pt[tid] = acc;
            __syncthreads();
            if (tid < 128){
                float v = s_pt[tid] + s_pt[tid+128] + s_pt[tid+256] + s_pt[tid+384]
                        + s_trr[tid];
                s_rn[tid] = v;
            }
        }
        CLUSTER_SYNC();

        if (t < TT-1){
            s_r[tid] = dsmem_ld(s2u(&s_rn[tid & 127]), (unsigned int)(tid >> 7));
            __syncthreads();
        }
    }

    // ===== merged final_g: g = rg(r) + rg_b + qg(qh) + qg_b =====
    {
        // gather full final r (peers' s_rn valid: written before last CLUSTER_SYNC)
        s_r[tid] = dsmem_ld(s2u(&s_rn[tid & 127]), (unsigned int)(tid >> 7));
        float* s_qh = s_lp;                 // 512 floats (s_lp + s_lgf contiguous)
        s_qh[tid] = qh[b*512 + tid];
        __syncthreads();

#pragma unroll 1
        for (int i = 0; i < 8; i++){
            int e = (int)rank*128 + warp*8 + i;
            const float* w1 = rg_w + (size_t)e*512;
            const float* w2 = qg_w + (size_t)e*512;
            float s = 0.f;
#pragma unroll
            for (int j = 0; j < 4; j++){
                int k = j*128 + lane*4;
                float4 a = *(const float4*)(w1 + k);
                float4 x = *(const float4*)(s_r + k);
                float4 c = *(const float4*)(w2 + k);
                float4 y = *(const float4*)(s_qh + k);
                s += a.x*x.x + a.y*x.y + a.z*x.z + a.w*x.w;
                s += c.x*y.x + c.y*y.y + c.z*y.z + c.w*y.w;
            }
            s = warp_sum(s);
            if (lane == 0) out[b*512 + e] = s + rg_b[e] + qg_b[e];
        }
    }

    CLUSTER_SYNC();   // no CTA exits while a peer may still read its SMEM
}

// ---------------- host launch ----------------
extern "C" void kernel_launch(void* const* d_in, const int* in_sizes, int n_in,
                              void* d_out, int out_size)
{
    const float* ctx  = (const float*)d_in[0];
    const float* qout = (const float*)d_in[2];
    const float* qh   = (const float*)d_in[3];
    const float* img  = (const float*)d_in[4];
    const float* fc1w = (const float*)d_in[6];  const float* fc1b = (const float*)d_in[7];
    const float* fc2w = (const float*)d_in[8];  const float* fc2b = (const float*)d_in[9];
    const float* dmw  = (const float*)d_in[10]; const float* dmb  = (const float*)d_in[11];
    const float* msw  = (const float*)d_in[12]; const float* msb  = (const float*)d_in[13];
    const float* rmw  = (const float*)d_in[14]; const float* rmb  = (const float*)d_in[15];
    const float* qmw  = (const float*)d_in[16]; const float* qmb  = (const float*)d_in[17];
    const float* rrw  = (const float*)d_in[18]; const float* rrb  = (const float*)d_in[19];
    const float* rgw  = (const float*)d_in[20]; const float* rgb  = (const float*)d_in[21];
    const float* qgw  = (const float*)d_in[22]; const float* qgb  = (const float*)d_in[23];

    cudaFuncSetAttribute(scan_cluster, cudaFuncAttributeMaxDynamicSharedMemorySize,
                         SMEM_SCAN_BYTES);
    cudaFuncSetAttribute(codm_mma, cudaFuncAttributeMaxDynamicSharedMemorySize,
                         CODM_SMEM_BYTES);

    // MEGA launch: co GEMM + qm GEMM + all weight conversions
    gemm_A<<<1120, 256>>>(ctx, img, fc1w, fc1b, fc2w, fc2b,
                          qout, qmw, qmb, rmw, rrw, dmw);

    // codm = co @ dm_w^T + dm_b via split-bf16 HMMA (cp.async staging)
    codm_mma<<<256, 256, CODM_SMEM_BYTES>>>(dmb);

    // scan (incl. merged final output projection)
    scan_cluster<<<128, 512, SMEM_SCAN_BYTES>>>(rmb, rrb, msw, msb,
                                                rgw, rgb, qgw, qgb, qh,
                                                (float*)d_out);
}

// round 16
// speedup vs baseline: 1.2613x; 1.1005x over previous
#include <cuda_runtime.h>
#include <cuda_bf16.h>
#include <cstdint>
#include <math.h>

#define DD 512
#define SS 256
#define BB 32
#define TT 24
#define NROWS (BB*SS)   // 8192

#define CROWS 208
// dynamic smem layout (float offsets) — scan kernel
#define OFF_WC   0
#define OFF_R    (CROWS*256)
#define OFF_ADD  (OFF_R + 512)
#define OFF_TRR  (OFF_ADD + 128)
#define OFF_LP   (OFF_TRR + 128)
#define OFF_LGF  (OFF_LP + 256)
#define OFF_RED  (OFF_LGF + 256)
#define OFF_SW   (OFF_RED + 32)
#define OFF_PT   (OFF_SW + 256)
#define OFF_RN   (OFF_PT + 512)
#define OFF_MW   (OFF_RN + 128)
#define OFF_PB   (OFF_MW + 128)
#define SMEM_SCAN_FLOATS (OFF_PB + 256)
#define SMEM_SCAN_BYTES  (SMEM_SCAN_FLOATS*4)

#define MPAD 72
#define MMA_SMEM_BYTES (4*128*MPAD*2)   // Ah,Al,Bh,Bl tiles = 73728 B

// ---------------- device scratch ----------------
__device__ float g_co[NROWS*512];
__device__ __nv_bfloat16 g_cohi[NROWS*512];
__device__ __nv_bfloat16 g_colo[NROWS*512];
__device__ __nv_bfloat16 g_codm[NROWS*512];
__device__ float g_qm[TT*BB*512];
__device__ __nv_bfloat16 g_wbf[1024*512];          // [rm_w | rr_w] bf16 (scan)
__device__ __nv_bfloat16 g_dmhi[512*512];
__device__ __nv_bfloat16 g_dmlo[512*512];

// ---------------- helpers ----------------
__device__ __forceinline__ float tanh_mufu(float x){
    float y;
    asm("tanh.approx.f32 %0, %1;" : "=f"(y) : "f"(x));
    return y;
}

__device__ __forceinline__ float warp_sum(float v){
#pragma unroll
    for (int o = 16; o; o >>= 1) v += __shfl_xor_sync(0xffffffffu, v, o);
    return v;
}

__device__ __forceinline__ unsigned int s2u(const void* p){
    unsigned int a;
    asm("{ .reg .u64 t; cvta.to.shared.u64 t, %1; cvt.u32.u64 %0, t; }" : "=r"(a) : "l"(p));
    return a;
}

__device__ __forceinline__ float dsmem_ld(unsigned int saddr, unsigned int rank){
    unsigned int ra; float v;
    asm volatile("mapa.shared::cluster.u32 %0, %1, %2;" : "=r"(ra) : "r"(saddr), "r"(rank));
    asm volatile("ld.shared::cluster.f32 %0, [%1];" : "=f"(v) : "r"(ra) : "memory");
    return v;
}

#define CLUSTER_SYNC() do{ \
    asm volatile("barrier.cluster.arrive.aligned;" ::: "memory"); \
    asm volatile("barrier.cluster.wait.aligned;"   ::: "memory"); }while(0)

__device__ __forceinline__ void cpa16(unsigned int s, const void* g){
    asm volatile("cp.async.cg.shared.global [%0], [%1], 16;" :: "r"(s), "l"(g));
}
#define CPA_WAIT() asm volatile("cp.async.commit_group;\n\tcp.async.wait_group 0;" ::: "memory")

// split 4 fp32 -> 4 hi-bf16 (uint2) + 4 lo-bf16 (uint2)
__device__ __forceinline__ void split4(float4 f, uint2* ho, uint2* lo){
    __nv_bfloat16 h[4], l[4];
    float fv[4] = {f.x, f.y, f.z, f.w};
#pragma unroll
    for (int j = 0; j < 4; j++){
        h[j] = __float2bfloat16(fv[j]);
        l[j] = __float2bfloat16(fv[j] - __bfloat162float(h[j]));
    }
    *ho = *(uint2*)h; *lo = *(uint2*)l;
}

// dot of 16 bf16 weights with 16 fp32 r values
__device__ __forceinline__ float dot16(uint4 u0, uint4 u1, const float* r){
    float s = 0.f; float2 c;
    c = __bfloat1622float2(*(const __nv_bfloat162*)&u0.x); s += c.x*r[0]  + c.y*r[1];
    c = __bfloat1622float2(*(const __nv_bfloat162*)&u0.y); s += c.x*r[2]  + c.y*r[3];
    c = __bfloat1622float2(*(const __nv_bfloat162*)&u0.z); s += c.x*r[4]  + c.y*r[5];
    c = __bfloat1622float2(*(const __nv_bfloat162*)&u0.w); s += c.x*r[6]  + c.y*r[7];
    c = __bfloat1622float2(*(const __nv_bfloat162*)&u1.x); s += c.x*r[8]  + c.y*r[9];
    c = __bfloat1622float2(*(const __nv_bfloat162*)&u1.y); s += c.x*r[10] + c.y*r[11];
    c = __bfloat1622float2(*(const __nv_bfloat162*)&u1.z); s += c.x*r[12] + c.y*r[13];
    c = __bfloat1622float2(*(const __nv_bfloat162*)&u1.w); s += c.x*r[14] + c.y*r[15];
    return s;
}

// ---- shared MMA tile-compute: 3-term split over one staged 64-K chunk ----
__device__ __forceinline__ void mma_chunk(__nv_bfloat16* sAh, __nv_bfloat16* sAl,
                                          __nv_bfloat16* sBh, __nv_bfloat16* sBl,
                                          float acc[2][8][4], int wr, int wc,
                                          int ldrow, int ldcol){
#pragma unroll
    for (int ks = 0; ks < 4; ks++){
        unsigned int ah[2][4], al[2][4];
#pragma unroll
        for (int mt = 0; mt < 2; mt++){
            unsigned int adh = s2u(&sAh[(wr*32 + mt*16 + ldrow)*MPAD + ks*16 + ldcol]);
            asm volatile("ldmatrix.sync.aligned.m8n8.x4.shared.b16 {%0,%1,%2,%3}, [%4];"
                         : "=r"(ah[mt][0]), "=r"(ah[mt][1]), "=r"(ah[mt][2]), "=r"(ah[mt][3])
                         : "r"(adh));
            unsigned int adl = s2u(&sAl[(wr*32 + mt*16 + ldrow)*MPAD + ks*16 + ldcol]);
            asm volatile("ldmatrix.sync.aligned.m8n8.x4.shared.b16 {%0,%1,%2,%3}, [%4];"
                         : "=r"(al[mt][0]), "=r"(al[mt][1]), "=r"(al[mt][2]), "=r"(al[mt][3])
                         : "r"(adl));
        }
        unsigned int bfr[8][2];
#pragma unroll
        for (int nb = 0; nb < 4; nb++){
            unsigned int bd = s2u(&sBh[(wc*64 + nb*16 + ldrow)*MPAD + ks*16 + ldcol]);
            unsigned int r0, r1, r2, r3;
            asm volatile("ldmatrix.sync.aligned.m8n8.x4.shared.b16 {%0,%1,%2,%3}, [%4];"
                         : "=r"(r0), "=r"(r1), "=r"(r2), "=r"(r3) : "r"(bd));
            bfr[nb*2][0]   = r0; bfr[nb*2][1]   = r2;
            bfr[nb*2+1][0] = r1; bfr[nb*2+1][1] = r3;
        }
#pragma unroll
        for (int mt = 0; mt < 2; mt++)
#pragma unroll
            for (int nt = 0; nt < 8; nt++){
                asm volatile(
                    "mma.sync.aligned.m16n8k16.row.col.f32.bf16.bf16.f32 "
                    "{%0,%1,%2,%3}, {%4,%5,%6,%7}, {%8,%9}, {%0,%1,%2,%3};"
                    : "+f"(acc[mt][nt][0]), "+f"(acc[mt][nt][1]),
                      "+f"(acc[mt][nt][2]), "+f"(acc[mt][nt][3])
                    : "r"(ah[mt][0]), "r"(ah[mt][1]), "r"(ah[mt][2]), "r"(ah[mt][3]),
                      "r"(bfr[nt][0]), "r"(bfr[nt][1]));
                asm volatile(
                    "mma.sync.aligned.m16n8k16.row.col.f32.bf16.bf16.f32 "
                    "{%0,%1,%2,%3}, {%4,%5,%6,%7}, {%8,%9}, {%0,%1,%2,%3};"
                    : "+f"(acc[mt][nt][0]), "+f"(acc[mt][nt][1]),
                      "+f"(acc[mt][nt][2]), "+f"(acc[mt][nt][3])
                    : "r"(al[mt][0]), "r"(al[mt][1]), "r"(al[mt][2]), "r"(al[mt][3]),
                      "r"(bfr[nt][0]), "r"(bfr[nt][1]));
            }
#pragma unroll
        for (int nb = 0; nb < 4; nb++){
            unsigned int bd = s2u(&sBl[(wc*64 + nb*16 + ldrow)*MPAD + ks*16 + ldcol]);
            unsigned int r0, r1, r2, r3;
            asm volatile("ldmatrix.sync.aligned.m8n8.x4.shared.b16 {%0,%1,%2,%3}, [%4];"
                         : "=r"(r0), "=r"(r1), "=r"(r2), "=r"(r3) : "r"(bd));
            bfr[nb*2][0]   = r0; bfr[nb*2][1]   = r2;
            bfr[nb*2+1][0] = r1; bfr[nb*2+1][1] = r3;
        }
#pragma unroll
        for (int mt = 0; mt < 2; mt++)
#pragma unroll
            for (int nt = 0; nt < 8; nt++){
                asm volatile(
                    "mma.sync.aligned.m16n8k16.row.col.f32.bf16.bf16.f32 "
                    "{%0,%1,%2,%3}, {%4,%5,%6,%7}, {%8,%9}, {%0,%1,%2,%3};"
                    : "+f"(acc[mt][nt][0]), "+f"(acc[mt][nt][1]),
                      "+f"(acc[mt][nt][2]), "+f"(acc[mt][nt][3])
                    : "r"(ah[mt][0]), "r"(ah[mt][1]), "r"(ah[mt][2]), "r"(ah[mt][3]),
                      "r"(bfr[nt][0]), "r"(bfr[nt][1]));
            }
    }
}

// ---------------- MEGA launch A: co (split-HMMA) + qm GEMM + weight conversions ----------------
// blocks [0,256):    co = perm(ctx)@fc1^T + perm(img)@fc2^T + (fc1b+fc2b)  [tensor pipe]
// blocks [256,352):  qm = qout@qm_w^T + qm_b                                [FFMA]
// blocks [352,1120): conversions: rm/rr -> g_wbf; dm -> hi/lo
__global__ __launch_bounds__(256) void gemm_A(const float* __restrict__ ctx,
                                              const float* __restrict__ img,
                                              const float* __restrict__ fc1w,
                                              const float* __restrict__ fc1b,
                                              const float* __restrict__ fc2w,
                                              const float* __restrict__ fc2b,
                                              const float* __restrict__ qout,
                                              const float* __restrict__ qmw,
                                              const float* __restrict__ qmb,
                                              const float* __restrict__ rm_w,
                                              const float* __restrict__ rr_w,
                                              const float* __restrict__ dm_w)
{
    extern __shared__ char smraw[];
    const int bid = blockIdx.x;
    const int tid = threadIdx.x;

    if (bid < 256){
        __nv_bfloat16* sAh = (__nv_bfloat16*)smraw;
        __nv_bfloat16* sAl = sAh + 128*MPAD;
        __nv_bfloat16* sBh = sAh + 2*128*MPAD;
        __nv_bfloat16* sBl = sAh + 3*128*MPAD;

        const int warp = tid >> 5, lane = tid & 31;
        const int m0 = (bid >> 2) * 128;
        const int n0 = (bid & 3) * 128;
        const int wr = warp >> 1;
        const int wc = warp & 1;
        const int ldrow = lane & 15;
        const int ldcol = (lane >> 4) * 8;

        // per-thread staging coords: 8 iterations cover 128 rows x 16 col-groups
        const int srow = tid >> 1;            // 0..127 (row, 2 threads per row)
        const int scg  = (tid & 1) * 8;       // col group base (x4 floats): 0 or 8

        // permuted A source row
        const int gm = m0 + srow;
        const int pr = (gm & 255)*32 + (gm >> 8);

        float acc[2][8][4];
#pragma unroll
        for (int i = 0; i < 2; i++)
#pragma unroll
            for (int j = 0; j < 8; j++)
#pragma unroll
                for (int k = 0; k < 4; k++) acc[i][j][k] = 0.f;

#pragma unroll 1
        for (int kc = 0; kc < 16; kc++){
            const int hh = kc >> 3;
            const int kk = (kc & 7) * 64;
            const float* asrc = (hh ? img  : ctx)  + (size_t)pr*512 + kk;
            const float* bsrc = (hh ? fc2w : fc1w) + (size_t)(n0 + srow)*512 + kk;
            __syncthreads();
#pragma unroll
            for (int cg = 0; cg < 8; cg++){
                int c = (scg + cg) * 4;      // 0..60 step 4
                float4 fa = *(const float4*)(asrc + c);
                uint2 ho, lo;
                split4(fa, &ho, &lo);
                *(uint2*)&sAh[srow*MPAD + c] = ho;
                *(uint2*)&sAl[srow*MPAD + c] = lo;
                float4 fb = *(const float4*)(bsrc + c);
                split4(fb, &ho, &lo);
                *(uint2*)&sBh[srow*MPAD + c] = ho;
                *(uint2*)&sBl[srow*MPAD + c] = lo;
            }
            __syncthreads();
            mma_chunk(sAh, sAl, sBh, sBl, acc, wr, wc, ldrow, ldcol);
        }

        // epilogue
        const int g  = lane >> 2;
        const int cc = (lane & 3) * 2;
#pragma unroll
        for (int mt = 0; mt < 2; mt++){
#pragma unroll
            for (int nt = 0; nt < 8; nt++){
                int n = n0 + wc*64 + nt*8 + cc;
                float b0 = fc1b[n]   + fc2b[n];
                float b1 = fc1b[n+1] + fc2b[n+1];
                int r0 = m0 + wr*32 + mt*16 + g;
#pragma unroll
                for (int rr2 = 0; rr2 < 2; rr2++){
                    int m = r0 + rr2*8;
                    float v0 = acc[mt][nt][rr2*2]   + b0;
                    float v1 = acc[mt][nt][rr2*2+1] + b1;
                    *(float2*)&g_co[(size_t)m*512 + n] = make_float2(v0, v1);
                    __nv_bfloat16 h0 = __float2bfloat16(v0);
                    __nv_bfloat16 h1 = __float2bfloat16(v1);
                    __nv_bfloat16 l0 = __float2bfloat16(v0 - __bfloat162float(h0));
                    __nv_bfloat16 l1 = __float2bfloat16(v1 - __bfloat162float(h1));
                    __nv_bfloat16 hp[2] = {h0, h1}, lp[2] = {l0, l1};
                    *(unsigned*)&g_cohi[(size_t)m*512 + n] = *(unsigned*)hp;
                    *(unsigned*)&g_colo[(size_t)m*512 + n] = *(unsigned*)lp;
                }
            }
        }
    } else if (bid < 352){
        float* As = (float*)smraw;            // stride 68
        float* Bs = As + 16*68;
        const int qid = bid - 256;
        const int m0  = (qid >> 3) * 64;
        const int n0  = (qid & 7) * 64;
        const int tx  = tid & 15, ty = tid >> 4;
        const int lr0 = tid >> 2;
        const int lc4 = (tid & 3) * 4;

        float acc[4][4] = {};
        const float* A1 = qout + (size_t)(m0 + lr0)*512 + lc4;
        const float* W1 = qmw  + (size_t)(n0 + lr0)*512 + lc4;

        for (int kt = 0; kt < 512; kt += 16){
            float4 a0 = *(const float4*)(A1 + kt);
            float4 w0 = *(const float4*)(W1 + kt);
            __syncthreads();
            As[(lc4+0)*68 + lr0] = a0.x; As[(lc4+1)*68 + lr0] = a0.y;
            As[(lc4+2)*68 + lr0] = a0.z; As[(lc4+3)*68 + lr0] = a0.w;
            Bs[(lc4+0)*68 + lr0] = w0.x; Bs[(lc4+1)*68 + lr0] = w0.y;
            Bs[(lc4+2)*68 + lr0] = w0.z; Bs[(lc4+3)*68 + lr0] = w0.w;
            __syncthreads();
#pragma unroll
            for (int k = 0; k < 16; k++){
                float4 av = *(const float4*)&As[k*68 + ty*4];
                float4 bv = *(const float4*)&Bs[k*68 + tx*4];
                float aa[4] = {av.x,av.y,av.z,av.w};
                float bb[4] = {bv.x,bv.y,bv.z,bv.w};
#pragma unroll
                for (int i = 0; i < 4; i++)
#pragma unroll
                    for (int j = 0; j < 4; j++)
                        acc[i][j] = fmaf(aa[i], bb[j], acc[i][j]);
            }
        }

        float4 bq = *(const float4*)&qmb[n0 + tx*4];
        float bj[4] = {bq.x,bq.y,bq.z,bq.w};
#pragma unroll
        for (int i = 0; i < 4; i++){
            int m = m0 + ty*4 + i;
            float4 o = make_float4(acc[i][0]+bj[0], acc[i][1]+bj[1],
                                   acc[i][2]+bj[2], acc[i][3]+bj[3]);
            *(float4*)&g_qm[(size_t)m*512 + n0 + tx*4] = o;
        }
    } else {
        int v = (bid - 352) * 256 + tid;       // 0..196607
        if (v < 131072){
            const float* src = (v < 65536) ? rm_w : rr_w;
            __nv_bfloat16* dst = (v < 65536) ? g_wbf : (g_wbf + (size_t)512*512);
            int i = v & 65535;
            float4 f = ((const float4*)src)[i];
            __nv_bfloat162 p0 = __floats2bfloat162_rn(f.x, f.y);
            __nv_bfloat162 p1 = __floats2bfloat162_rn(f.z, f.w);
            ((uint2*)dst)[i] = make_uint2(*(unsigned*)&p0, *(unsigned*)&p1);
        } else {
            int i = v - 131072;
            float4 f = ((const float4*)dm_w)[i];
            uint2 ho, lo;
            split4(f, &ho, &lo);
            ((uint2*)g_dmhi)[i] = ho;
            ((uint2*)g_dmlo)[i] = lo;
        }
    }
}

// ---------------- codm via split-bf16 mma.sync (cp.async staging) ----------------
__global__ __launch_bounds__(256) void codm_mma(const float* __restrict__ bias)
{
    extern __shared__ __nv_bfloat16 smb[];
    __nv_bfloat16* sAh = smb;
    __nv_bfloat16* sAl = smb + 128*MPAD;
    __nv_bfloat16* sBh = smb + 2*128*MPAD;
    __nv_bfloat16* sBl = smb + 3*128*MPAD;

    const int tid  = threadIdx.x;
    const int warp = tid >> 5, lane = tid & 31;
    const int m0 = (int)(blockIdx.x >> 2) * 128;
    const int n0 = (int)(blockIdx.x & 3) * 128;
    const int wr = warp >> 1;
    const int wc = warp & 1;

    float acc[2][8][4];
#pragma unroll
    for (int i = 0; i < 2; i++)
#pragma unroll
        for (int j = 0; j < 8; j++)
#pragma unroll
            for (int k = 0; k < 4; k++) acc[i][j][k] = 0.f;

    const int ldrow = lane & 15;
    const int ldcol = (lane >> 4) * 8;

#pragma unroll 1
    for (int kc = 0; kc < 8; kc++){
#pragma unroll
        for (int t = 0; t < 4; t++){
            int i = tid + t*256;
            int r = i >> 3, c = (i & 7) * 8;
            size_t ga = (size_t)(m0 + r)*512 + kc*64 + c;
            size_t gb = (size_t)(n0 + r)*512 + kc*64 + c;
            unsigned so = (unsigned)((r*MPAD + c) * 2);
            cpa16(s2u(sAh) + so, &g_cohi[ga]);
            cpa16(s2u(sAl) + so, &g_colo[ga]);
            cpa16(s2u(sBh) + so, &g_dmhi[gb]);
            cpa16(s2u(sBl) + so, &g_dmlo[gb]);
        }
        CPA_WAIT();
        __syncthreads();
        mma_chunk(sAh, sAl, sBh, sBl, acc, wr, wc, ldrow, ldcol);
        __syncthreads();
    }

    const int g  = lane >> 2;
    const int cc = (lane & 3) * 2;
#pragma unroll
    for (int mt = 0; mt < 2; mt++){
#pragma unroll
        for (int nt = 0; nt < 8; nt++){
            int n = n0 + wc*64 + nt*8 + cc;
            float b0 = bias[n], b1 = bias[n+1];
            int r0 = m0 + wr*32 + mt*16 + g;
            __nv_bfloat162 p0 = __floats2bfloat162_rn(acc[mt][nt][0] + b0,
                                                      acc[mt][nt][1] + b1);
            *(__nv_bfloat162*)&g_codm[(size_t)r0*512 + n] = p0;
            __nv_bfloat162 p1 = __floats2bfloat162_rn(acc[mt][nt][2] + b0,
                                                      acc[mt][nt][3] + b1);
            *(__nv_bfloat162*)&g_codm[(size_t)(r0+8)*512 + n] = p1;
        }
    }
}

// ---------------- persistent cluster scan (+ merged final_g epilogue) ----------------
__global__ void __launch_bounds__(512, 1) __cluster_dims__(4, 1, 1)
scan_cluster(const float* __restrict__ rm_b, const float* __restrict__ rr_b,
             const float* __restrict__ ms_w, const float* __restrict__ ms_b,
             const float* __restrict__ rg_w, const float* __restrict__ rg_b,
             const float* __restrict__ qg_w, const float* __restrict__ qg_b,
             const float* __restrict__ qh,   float* __restrict__ out)
{
    extern __shared__ float sm[];
    __nv_bfloat16* wc = (__nv_bfloat16*)(sm + OFF_WC);
    float* s_r   = sm + OFF_R;
    float* s_add = sm + OFF_ADD;
    float* s_trr = sm + OFF_TRR;
    float* s_lp  = sm + OFF_LP;
    float* s_lgf = sm + OFF_LGF;
    float* s_red = sm + OFF_RED;
    float* s_sw  = sm + OFF_SW;
    float* s_pt  = sm + OFF_PT;
    float* s_rn  = sm + OFF_RN;
    float* s_mw  = sm + OFF_MW;
    float* s_pb  = sm + OFF_PB;

    const int tid = threadIdx.x, lane = tid & 31, warp = tid >> 5;
    unsigned int rank; asm("mov.u32 %0, %%cluster_ctarank;" : "=r"(rank));
    const int b = blockIdx.x >> 2;

    const __nv_bfloat16* grm = g_wbf + (size_t)(rank*128)*512;
    const __nv_bfloat16* grr = g_wbf + (size_t)(512 + rank*128)*512;

    for (int idx = tid; idx < CROWS*64; idx += 512){
        int row = idx >> 6, c = idx & 63;
        const __nv_bfloat16* src = (row < 128) ? (grm + (size_t)row*512)
                                               : (grr + (size_t)(row-128)*512);
        ((uint4*)wc)[idx] = ((const uint4*)src)[c];
    }
    if (tid < 256) s_pb[tid] = (tid < 128) ? rm_b[rank*128 + tid]
                                           : rr_b[rank*128 + tid - 128];
    if (tid < 128) s_mw[tid] = ms_w[rank*128 + tid];
    s_r[tid] = 0.f;
    const float msb0 = ms_b[0];
    __syncthreads();

    for (int t = 0; t < TT; t++){
        float rreg[16];
#pragma unroll
        for (int i = 0; i < 4; i++)
            ((float4*)rreg)[i] = *(const float4*)&s_r[lane*16 + i*4];

        float qv[4] = {0.f,0.f,0.f,0.f};
        if (warp < 8 && lane < 4){
#pragma unroll
            for (int g = 0; g < 4; g++)
                qv[g] = g_qm[(size_t)(t*BB + b)*512 + rank*128 + warp*16 + g*4 + lane];
        }

        if (warp < 13){
#pragma unroll
            for (int g = 0; g < 4; g++){
                float sums[4];
#pragma unroll
                for (int q = 0; q < 4; q++){
                    const __nv_bfloat16* wp = wc + (size_t)(warp*16 + g*4 + q)*512 + lane*16;
                    uint4 u0 = *(const uint4*)wp;
                    uint4 u1 = *(const uint4*)(wp + 8);
                    sums[q] = dot16(u0, u1, rreg);
                }
#pragma unroll
                for (int q = 0; q < 4; q++) sums[q] = warp_sum(sums[q]);
                if (lane < 4){
                    float v = (lane==0)?sums[0]:(lane==1)?sums[1]:(lane==2)?sums[2]:sums[3];
                    int row = warp*16 + g*4 + lane;
                    v += s_pb[row];
                    if (warp < 8) s_add[row]       = v + qv[g];
                    else          s_trr[row - 128] = tanh_mufu(v);
                }
            }
        } else {
#pragma unroll
            for (int g = 0; g < 4; g++){
                uint4 u[4][2];
#pragma unroll
                for (int q = 0; q < 4; q++){
                    const __nv_bfloat16* wp = grr + (size_t)(warp*16 + g*4 + q - 128)*512 + lane*16;
                    u[q][0] = *(const uint4*)wp;
                    u[q][1] = *(const uint4*)(wp + 8);
                }
                float sums[4];
#pragma unroll
                for (int q = 0; q < 4; q++) sums[q] = dot16(u[q][0], u[q][1], rreg);
#pragma unroll
                for (int q = 0; q < 4; q++) sums[q] = warp_sum(sums[q]);
                if (lane < 4){
                    float v = (lane==0)?sums[0]:(lane==1)?sums[1]:(lane==2)?sums[2]:sums[3];
                    int row = warp*16 + g*4 + lane;
                    s_trr[row - 128] = tanh_mufu(v + s_pb[row]);
                }
            }
        }
        __syncthreads();

        {
            float areg[4], mreg[4];
#pragma unroll
            for (int i = 0; i < 4; i++){
                areg[i] = s_add[lane*4 + i];
                mreg[i] = s_mw[lane*4 + i];
            }
#pragma unroll
            for (int g = 0; g < 4; g++){
                int s0 = warp*16 + g*4;
                float a4[4];
#pragma unroll
                for (int q = 0; q < 4; q++){
                    const __nv_bfloat16* cd = g_codm + (size_t)(b*256 + s0 + q)*512
                                            + rank*128 + lane*4;
                    uint2 u = *(const uint2*)cd;
                    float2 c01 = __bfloat1622float2(*(const __nv_bfloat162*)&u.x);
                    float2 c23 = __bfloat1622float2(*(const __nv_bfloat162*)&u.y);
                    a4[q] = tanh_mufu(c01.x + areg[0]) * mreg[0]
                          + tanh_mufu(c01.y + areg[1]) * mreg[1]
                          + tanh_mufu(c23.x + areg[2]) * mreg[2]
                          + tanh_mufu(c23.y + areg[3]) * mreg[3];
                }
#pragma unroll
                for (int q = 0; q < 4; q++) a4[q] = warp_sum(a4[q]);
                if (lane < 4){
                    float v = (lane==0)?a4[0]:(lane==1)?a4[1]:(lane==2)?a4[2]:a4[3];
                    s_lp[s0 + lane] = v;
                }
            }
        }
        CLUSTER_SYNC();

        if (tid < 256){
            unsigned int sa = s2u(&s_lp[tid]);
            float v = s_lp[tid] + msb0
                    + dsmem_ld(sa, (rank+1)&3u)
                    + dsmem_ld(sa, (rank+2)&3u)
                    + dsmem_ld(sa, (rank+3)&3u);
            s_lgf[tid] = v;
        }
        __syncthreads();

        {
            float l = s_lgf[tid & 255];
            float m = l;
#pragma unroll
            for (int o = 16; o; o >>= 1) m = fmaxf(m, __shfl_xor_sync(0xffffffffu, m, o));
            if (lane == 0) s_red[warp] = m;
            __syncthreads();
            float mx = s_red[0];
#pragma unroll
            for (int i = 1; i < 16; i++) mx = fmaxf(mx, s_red[i]);
            float ex = __expf(l - mx);
            float smm = warp_sum(ex);
            if (lane == 0) s_red[16 + warp] = smm;
            __syncthreads();
            float tot = s_red[16];
#pragma unroll
            for (int i = 17; i < 32; i++) tot += s_red[i];
            tot *= 0.5f;
            s_sw[tid & 255] = ex * (1.0f / tot);
        }
        __syncthreads();

        {
            int e  = (int)rank*128 + (tid & 127);
            int sq = tid >> 7;
            const float* cb = g_co + (size_t)(b*256 + sq*64)*512 + e;
            const float* wv = s_sw + sq*64;
            float acc = 0.f;
#pragma unroll 16
            for (int s = 0; s < 64; s++)
                acc = fmaf(wv[s], cb[(size_t)s*512], acc);
            s_pt[tid] = acc;
            __syncthreads();
            if (tid < 128){
                float v = s_pt[tid] + s_pt[tid+128] + s_pt[tid+256] + s_pt[tid+384]
                        + s_trr[tid];
                s_rn[tid] = v;
            }
        }
        CLUSTER_SYNC();

        if (t < TT-1){
            s_r[tid] = dsmem_ld(s2u(&s_rn[tid & 127]), (unsigned int)(tid >> 7));
            __syncthreads();
        }
    }

    // ===== merged final_g =====
    {
        s_r[tid] = dsmem_ld(s2u(&s_rn[tid & 127]), (unsigned int)(tid >> 7));
        float* s_qh = s_lp;
        s_qh[tid] = qh[b*512 + tid];
        __syncthreads();

#pragma unroll 1
        for (int i = 0; i < 8; i++){
            int e = (int)rank*128 + warp*8 + i;
            const float* w1 = rg_w + (size_t)e*512;
            const float* w2 = qg_w + (size_t)e*512;
            float s = 0.f;
#pragma unroll
            for (int j = 0; j < 4; j++){
                int k = j*128 + lane*4;
                float4 a = *(const float4*)(w1 + k);
                float4 x = *(const float4*)(s_r + k);
                float4 c = *(const float4*)(w2 + k);
                float4 y = *(const float4*)(s_qh + k);
                s += a.x*x.x + a.y*x.y + a.z*x.z + a.w*x.w;
                s += c.x*y.x + c.y*y.y + c.z*y.z + c.w*y.w;
            }
            s = warp_sum(s);
            if (lane == 0) out[b*512 + e] = s + rg_b[e] + qg_b[e];
        }
    }

    CLUSTER_SYNC();
}

// ---------------- host launch ----------------
extern "C" void kernel_launch(void* const* d_in, const int* in_sizes, int n_in,
                              void* d_out, int out_size)
{
    const float* ctx  = (const float*)d_in[0];
    const float* qout = (const float*)d_in[2];
    const float* qh   = (const float*)d_in[3];
    const float* img  = (const float*)d_in[4];
    const float* fc1w = (const float*)d_in[6];  const float* fc1b = (const float*)d_in[7];
    const float* fc2w = (const float*)d_in[8];  const float* fc2b = (const float*)d_in[9];
    const float* dmw  = (const float*)d_in[10]; const float* dmb  = (const float*)d_in[11];
    const float* msw  = (const float*)d_in[12]; const float* msb  = (const float*)d_in[13];
    const float* rmw  = (const float*)d_in[14]; const float* rmb  = (const float*)d_in[15];
    const float* qmw  = (const float*)d_in[16]; const float* qmb  = (const float*)d_in[17];
    const float* rrw  = (const float*)d_in[18]; const float* rrb  = (const float*)d_in[19];
    const float* rgw  = (const float*)d_in[20]; const float* rgb  = (const float*)d_in[21];
    const float* qgw  = (const float*)d_in[22]; const float* qgb  = (const float*)d_in[23];

    cudaFuncSetAttribute(scan_cluster, cudaFuncAttributeMaxDynamicSharedMemorySize,
                         SMEM_SCAN_BYTES);
    cudaFuncSetAttribute(codm_mma, cudaFuncAttributeMaxDynamicSharedMemorySize,
                         MMA_SMEM_BYTES);
    cudaFuncSetAttribute(gemm_A, cudaFuncAttributeMaxDynamicSharedMemorySize,
                         MMA_SMEM_BYTES);

    // MEGA launch: co (split-HMMA) + qm GEMM + all weight conversions
    gemm_A<<<1120, 256, MMA_SMEM_BYTES>>>(ctx, img, fc1w, fc1b, fc2w, fc2b,
                                          qout, qmw, qmb, rmw, rrw, dmw);

    // codm = co @ dm_w^T + dm_b via split-bf16 HMMA (cp.async staging)
    codm_mma<<<256, 256, MMA_SMEM_BYTES>>>(dmb);

    // scan (incl. merged final output projection)
    scan_cluster<<<128, 512, SMEM_SCAN_BYTES>>>(rmb, rrb, msw, msb,
                                                rgw, rgb, qgw, qgb, qh,
                                                (float*)d_out);
}

// round 17
// speedup vs baseline: 1.3403x; 1.0626x over previous
#include <cuda_runtime.h>
#include <cuda_bf16.h>
#include <cstdint>
#include <math.h>

#define DD 512
#define SS 256
#define BB 32
#define TT 24
#define NROWS (BB*SS)   // 8192

#define CROWS 208
// dynamic smem layout (float offsets) — scan kernel
#define OFF_WC   0
#define OFF_R    (CROWS*256)
#define OFF_ADD  (OFF_R + 512)
#define OFF_TRR  (OFF_ADD + 128)
#define OFF_LP   (OFF_TRR + 128)
#define OFF_LGF  (OFF_LP + 256)
#define OFF_RED  (OFF_LGF + 256)
#define OFF_SW   (OFF_RED + 32)
#define OFF_PT   (OFF_SW + 256)
#define OFF_RN   (OFF_PT + 512)
#define OFF_MW   (OFF_RN + 128)
#define OFF_PB   (OFF_MW + 128)
#define SMEM_SCAN_FLOATS (OFF_PB + 256)
#define SMEM_SCAN_BYTES  (SMEM_SCAN_FLOATS*4)

#define MPAD 72
#define TILEB (128*MPAD)                  // bf16 elems per tile
#define BUFB  (4*TILEB)                   // 4 tiles per buffer
#define MMA_SMEM_BYTES  (BUFB*2)          // one buffer  = 73728 B (codm)
#define MMA2_SMEM_BYTES (2*BUFB*2)        // two buffers = 147456 B (gemm_A)

// ---------------- device scratch ----------------
__device__ float g_co[NROWS*512];
__device__ __nv_bfloat16 g_cohi[NROWS*512];
__device__ __nv_bfloat16 g_colo[NROWS*512];
__device__ __nv_bfloat16 g_codm[NROWS*512];
__device__ float g_qm[TT*BB*512];
__device__ __nv_bfloat16 g_wbf[1024*512];
__device__ __nv_bfloat16 g_dmhi[512*512];
__device__ __nv_bfloat16 g_dmlo[512*512];

// ---------------- helpers ----------------
__device__ __forceinline__ float tanh_mufu(float x){
    float y;
    asm("tanh.approx.f32 %0, %1;" : "=f"(y) : "f"(x));
    return y;
}

__device__ __forceinline__ float warp_sum(float v){
#pragma unroll
    for (int o = 16; o; o >>= 1) v += __shfl_xor_sync(0xffffffffu, v, o);
    return v;
}

__device__ __forceinline__ unsigned int s2u(const void* p){
    unsigned int a;
    asm("{ .reg .u64 t; cvta.to.shared.u64 t, %1; cvt.u32.u64 %0, t; }" : "=r"(a) : "l"(p));
    return a;
}

__device__ __forceinline__ float dsmem_ld(unsigned int saddr, unsigned int rank){
    unsigned int ra; float v;
    asm volatile("mapa.shared::cluster.u32 %0, %1, %2;" : "=r"(ra) : "r"(saddr), "r"(rank));
    asm volatile("ld.shared::cluster.f32 %0, [%1];" : "=f"(v) : "r"(ra) : "memory");
    return v;
}

#define CLUSTER_SYNC() do{ \
    asm volatile("barrier.cluster.arrive.aligned;" ::: "memory"); \
    asm volatile("barrier.cluster.wait.aligned;"   ::: "memory"); }while(0)

__device__ __forceinline__ void cpa16(unsigned int s, const void* g){
    asm volatile("cp.async.cg.shared.global [%0], [%1], 16;" :: "r"(s), "l"(g));
}
#define CPA_WAIT() asm volatile("cp.async.commit_group;\n\tcp.async.wait_group 0;" ::: "memory")

// split 4 fp32 -> hi/lo bf16
__device__ __forceinline__ void split4(float4 f, uint2* ho, uint2* lo){
    __nv_bfloat16 h[4], l[4];
    float fv[4] = {f.x, f.y, f.z, f.w};
#pragma unroll
    for (int j = 0; j < 4; j++){
        h[j] = __float2bfloat16(fv[j]);
        l[j] = __float2bfloat16(fv[j] - __bfloat162float(h[j]));
    }
    *ho = *(uint2*)h; *lo = *(uint2*)l;
}

__device__ __forceinline__ float dot16(uint4 u0, uint4 u1, const float* r){
    float s = 0.f; float2 c;
    c = __bfloat1622float2(*(const __nv_bfloat162*)&u0.x); s += c.x*r[0]  + c.y*r[1];
    c = __bfloat1622float2(*(const __nv_bfloat162*)&u0.y); s += c.x*r[2]  + c.y*r[3];
    c = __bfloat1622float2(*(const __nv_bfloat162*)&u0.z); s += c.x*r[4]  + c.y*r[5];
    c = __bfloat1622float2(*(const __nv_bfloat162*)&u0.w); s += c.x*r[6]  + c.y*r[7];
    c = __bfloat1622float2(*(const __nv_bfloat162*)&u1.x); s += c.x*r[8]  + c.y*r[9];
    c = __bfloat1622float2(*(const __nv_bfloat162*)&u1.y); s += c.x*r[10] + c.y*r[11];
    c = __bfloat1622float2(*(const __nv_bfloat162*)&u1.z); s += c.x*r[12] + c.y*r[13];
    c = __bfloat1622float2(*(const __nv_bfloat162*)&u1.w); s += c.x*r[14] + c.y*r[15];
    return s;
}

// ---- 3-term split MMA over one staged 64-K chunk; warp tile 32x64 (codm) ----
__device__ __forceinline__ void mma_chunk(__nv_bfloat16* sAh, __nv_bfloat16* sAl,
                                          __nv_bfloat16* sBh, __nv_bfloat16* sBl,
                                          float acc[2][8][4], int wr, int wc,
                                          int ldrow, int ldcol){
#pragma unroll
    for (int ks = 0; ks < 4; ks++){
        unsigned int ah[2][4], al[2][4];
#pragma unroll
        for (int mt = 0; mt < 2; mt++){
            unsigned int adh = s2u(&sAh[(wr*32 + mt*16 + ldrow)*MPAD + ks*16 + ldcol]);
            asm volatile("ldmatrix.sync.aligned.m8n8.x4.shared.b16 {%0,%1,%2,%3}, [%4];"
                         : "=r"(ah[mt][0]), "=r"(ah[mt][1]), "=r"(ah[mt][2]), "=r"(ah[mt][3])
                         : "r"(adh));
            unsigned int adl = s2u(&sAl[(wr*32 + mt*16 + ldrow)*MPAD + ks*16 + ldcol]);
            asm volatile("ldmatrix.sync.aligned.m8n8.x4.shared.b16 {%0,%1,%2,%3}, [%4];"
                         : "=r"(al[mt][0]), "=r"(al[mt][1]), "=r"(al[mt][2]), "=r"(al[mt][3])
                         : "r"(adl));
        }
        unsigned int bfr[8][2];
#pragma unroll
        for (int nb = 0; nb < 4; nb++){
            unsigned int bd = s2u(&sBh[(wc*64 + nb*16 + ldrow)*MPAD + ks*16 + ldcol]);
            unsigned int r0, r1, r2, r3;
            asm volatile("ldmatrix.sync.aligned.m8n8.x4.shared.b16 {%0,%1,%2,%3}, [%4];"
                         : "=r"(r0), "=r"(r1), "=r"(r2), "=r"(r3) : "r"(bd));
            bfr[nb*2][0]   = r0; bfr[nb*2][1]   = r2;
            bfr[nb*2+1][0] = r1; bfr[nb*2+1][1] = r3;
        }
#pragma unroll
        for (int mt = 0; mt < 2; mt++)
#pragma unroll
            for (int nt = 0; nt < 8; nt++){
                asm volatile(
                    "mma.sync.aligned.m16n8k16.row.col.f32.bf16.bf16.f32 "
                    "{%0,%1,%2,%3}, {%4,%5,%6,%7}, {%8,%9}, {%0,%1,%2,%3};"
                    : "+f"(acc[mt][nt][0]), "+f"(acc[mt][nt][1]),
                      "+f"(acc[mt][nt][2]), "+f"(acc[mt][nt][3])
                    : "r"(ah[mt][0]), "r"(ah[mt][1]), "r"(ah[mt][2]), "r"(ah[mt][3]),
                      "r"(bfr[nt][0]), "r"(bfr[nt][1]));
                asm volatile(
                    "mma.sync.aligned.m16n8k16.row.col.f32.bf16.bf16.f32 "
                    "{%0,%1,%2,%3}, {%4,%5,%6,%7}, {%8,%9}, {%0,%1,%2,%3};"
                    : "+f"(acc[mt][nt][0]), "+f"(acc[mt][nt][1]),
                      "+f"(acc[mt][nt][2]), "+f"(acc[mt][nt][3])
                    : "r"(al[mt][0]), "r"(al[mt][1]), "r"(al[mt][2]), "r"(al[mt][3]),
                      "r"(bfr[nt][0]), "r"(bfr[nt][1]));
            }
#pragma unroll
        for (int nb = 0; nb < 4; nb++){
            unsigned int bd = s2u(&sBl[(wc*64 + nb*16 + ldrow)*MPAD + ks*16 + ldcol]);
            unsigned int r0, r1, r2, r3;
            asm volatile("ldmatrix.sync.aligned.m8n8.x4.shared.b16 {%0,%1,%2,%3}, [%4];"
                         : "=r"(r0), "=r"(r1), "=r"(r2), "=r"(r3) : "r"(bd));
            bfr[nb*2][0]   = r0; bfr[nb*2][1]   = r2;
            bfr[nb*2+1][0] = r1; bfr[nb*2+1][1] = r3;
        }
#pragma unroll
        for (int mt = 0; mt < 2; mt++)
#pragma unroll
            for (int nt = 0; nt < 8; nt++){
                asm volatile(
                    "mma.sync.aligned.m16n8k16.row.col.f32.bf16.bf16.f32 "
                    "{%0,%1,%2,%3}, {%4,%5,%6,%7}, {%8,%9}, {%0,%1,%2,%3};"
                    : "+f"(acc[mt][nt][0]), "+f"(acc[mt][nt][1]),
                      "+f"(acc[mt][nt][2]), "+f"(acc[mt][nt][3])
                    : "r"(ah[mt][0]), "r"(ah[mt][1]), "r"(ah[mt][2]), "r"(ah[mt][3]),
                      "r"(bfr[nt][0]), "r"(bfr[nt][1]));
            }
    }
}

// ---- same, warp tile 16x64 (gemm_A co blocks, 16 warps) ----
__device__ __forceinline__ void mma_chunk16(__nv_bfloat16* base, float acc[8][4],
                                            int wr, int wc, int ldrow, int ldcol){
    __nv_bfloat16* sAh = base;
    __nv_bfloat16* sAl = base + TILEB;
    __nv_bfloat16* sBh = base + 2*TILEB;
    __nv_bfloat16* sBl = base + 3*TILEB;
#pragma unroll
    for (int ks = 0; ks < 4; ks++){
        unsigned int ah[4], al[4];
        {
            unsigned int adh = s2u(&sAh[(wr*16 + ldrow)*MPAD + ks*16 + ldcol]);
            asm volatile("ldmatrix.sync.aligned.m8n8.x4.shared.b16 {%0,%1,%2,%3}, [%4];"
                         : "=r"(ah[0]), "=r"(ah[1]), "=r"(ah[2]), "=r"(ah[3]) : "r"(adh));
            unsigned int adl = s2u(&sAl[(wr*16 + ldrow)*MPAD + ks*16 + ldcol]);
            asm volatile("ldmatrix.sync.aligned.m8n8.x4.shared.b16 {%0,%1,%2,%3}, [%4];"
                         : "=r"(al[0]), "=r"(al[1]), "=r"(al[2]), "=r"(al[3]) : "r"(adl));
        }
        unsigned int bfr[8][2];
#pragma unroll
        for (int nb = 0; nb < 4; nb++){
            unsigned int bd = s2u(&sBh[(wc*64 + nb*16 + ldrow)*MPAD + ks*16 + ldcol]);
            unsigned int r0, r1, r2, r3;
            asm volatile("ldmatrix.sync.aligned.m8n8.x4.shared.b16 {%0,%1,%2,%3}, [%4];"
                         : "=r"(r0), "=r"(r1), "=r"(r2), "=r"(r3) : "r"(bd));
            bfr[nb*2][0]   = r0; bfr[nb*2][1]   = r2;
            bfr[nb*2+1][0] = r1; bfr[nb*2+1][1] = r3;
        }
#pragma unroll
        for (int nt = 0; nt < 8; nt++){
            asm volatile(
                "mma.sync.aligned.m16n8k16.row.col.f32.bf16.bf16.f32 "
                "{%0,%1,%2,%3}, {%4,%5,%6,%7}, {%8,%9}, {%0,%1,%2,%3};"
                : "+f"(acc[nt][0]), "+f"(acc[nt][1]), "+f"(acc[nt][2]), "+f"(acc[nt][3])
                : "r"(ah[0]), "r"(ah[1]), "r"(ah[2]), "r"(ah[3]),
                  "r"(bfr[nt][0]), "r"(bfr[nt][1]));
            asm volatile(
                "mma.sync.aligned.m16n8k16.row.col.f32.bf16.bf16.f32 "
                "{%0,%1,%2,%3}, {%4,%5,%6,%7}, {%8,%9}, {%0,%1,%2,%3};"
                : "+f"(acc[nt][0]), "+f"(acc[nt][1]), "+f"(acc[nt][2]), "+f"(acc[nt][3])
                : "r"(al[0]), "r"(al[1]), "r"(al[2]), "r"(al[3]),
                  "r"(bfr[nt][0]), "r"(bfr[nt][1]));
        }
#pragma unroll
        for (int nb = 0; nb < 4; nb++){
            unsigned int bd = s2u(&sBl[(wc*64 + nb*16 + ldrow)*MPAD + ks*16 + ldcol]);
            unsigned int r0, r1, r2, r3;
            asm volatile("ldmatrix.sync.aligned.m8n8.x4.shared.b16 {%0,%1,%2,%3}, [%4];"
                         : "=r"(r0), "=r"(r1), "=r"(r2), "=r"(r3) : "r"(bd));
            bfr[nb*2][0]   = r0; bfr[nb*2][1]   = r2;
            bfr[nb*2+1][0] = r1; bfr[nb*2+1][1] = r3;
        }
#pragma unroll
        for (int nt = 0; nt < 8; nt++){
            asm volatile(
                "mma.sync.aligned.m16n8k16.row.col.f32.bf16.bf16.f32 "
                "{%0,%1,%2,%3}, {%4,%5,%6,%7}, {%8,%9}, {%0,%1,%2,%3};"
                : "+f"(acc[nt][0]), "+f"(acc[nt][1]), "+f"(acc[nt][2]), "+f"(acc[nt][3])
                : "r"(ah[0]), "r"(ah[1]), "r"(ah[2]), "r"(ah[3]),
                  "r"(bfr[nt][0]), "r"(bfr[nt][1]));
        }
    }
}

// ---------------- MEGA launch A (512 thr): co pipelined HMMA + qm + conversions ----------------
// blocks [0,256):   co tiles (double-buffered, 16 warps, warp tile 16x64)
// blocks [256,352): qm (tid<256 active)
// blocks [352,736): conversions
__global__ __launch_bounds__(512) void gemm_A(const float* __restrict__ ctx,
                                              const float* __restrict__ img,
                                              const float* __restrict__ fc1w,
                                              const float* __restrict__ fc1b,
                                              const float* __restrict__ fc2w,
                                              const float* __restrict__ fc2b,
                                              const float* __restrict__ qout,
                                              const float* __restrict__ qmw,
                                              const float* __restrict__ qmb,
                                              const float* __restrict__ rm_w,
                                              const float* __restrict__ rr_w,
                                              const float* __restrict__ dm_w)
{
    extern __shared__ char smraw[];
    const int bid = blockIdx.x;
    const int tid = threadIdx.x;

    if (bid < 256){
        __nv_bfloat16* bufs[2] = { (__nv_bfloat16*)smraw,
                                   (__nv_bfloat16*)smraw + BUFB };

        const int warp = tid >> 5, lane = tid & 31;
        const int m0 = (bid >> 2) * 128;
        const int n0 = (bid & 3) * 128;
        const int wr = warp >> 1;          // 0..7
        const int wc = warp & 1;
        const int ldrow = lane & 15;
        const int ldcol = (lane >> 4) * 8;

        const int srow = tid >> 2;          // 0..127
        const int scg  = tid & 3;           // 4 col-groups of 16

        const int gm = m0 + srow;
        const int pr = (gm & 255)*32 + (gm >> 8);

        float acc[8][4];
#pragma unroll
        for (int j = 0; j < 8; j++)
#pragma unroll
            for (int k = 0; k < 4; k++) acc[j][k] = 0.f;

        float4 ra[4], rb[4];
        // prologue: load + stage chunk 0
        {
            const float* asrc = ctx  + (size_t)pr*512;
            const float* bsrc = fc1w + (size_t)(n0 + srow)*512;
#pragma unroll
            for (int cg = 0; cg < 4; cg++){
                int c = scg*16 + cg*4;
                ra[cg] = *(const float4*)(asrc + c);
                rb[cg] = *(const float4*)(bsrc + c);
            }
            __nv_bfloat16* b0 = bufs[0];
#pragma unroll
            for (int cg = 0; cg < 4; cg++){
                int c = scg*16 + cg*4;
                uint2 ho, lo;
                split4(ra[cg], &ho, &lo);
                *(uint2*)&b0[srow*MPAD + c]         = ho;
                *(uint2*)&b0[TILEB + srow*MPAD + c] = lo;
                split4(rb[cg], &ho, &lo);
                *(uint2*)&b0[2*TILEB + srow*MPAD + c] = ho;
                *(uint2*)&b0[3*TILEB + srow*MPAD + c] = lo;
            }
        }
        __syncthreads();

#pragma unroll 1
        for (int kc = 0; kc < 16; kc++){
            const bool has = (kc + 1 < 16);
            if (has){
                const int hh = (kc+1) >> 3;
                const int kk = ((kc+1) & 7) * 64;
                const float* asrc = (hh ? img  : ctx)  + (size_t)pr*512 + kk;
                const float* bsrc = (hh ? fc2w : fc1w) + (size_t)(n0 + srow)*512 + kk;
#pragma unroll
                for (int cg = 0; cg < 4; cg++){
                    int c = scg*16 + cg*4;
                    ra[cg] = *(const float4*)(asrc + c);
                    rb[cg] = *(const float4*)(bsrc + c);
                }
            }
            mma_chunk16(bufs[kc & 1], acc, wr, wc, ldrow, ldcol);
            if (has){
                __nv_bfloat16* nb = bufs[(kc+1) & 1];
#pragma unroll
                for (int cg = 0; cg < 4; cg++){
                    int c = scg*16 + cg*4;
                    uint2 ho, lo;
                    split4(ra[cg], &ho, &lo);
                    *(uint2*)&nb[srow*MPAD + c]         = ho;
                    *(uint2*)&nb[TILEB + srow*MPAD + c] = lo;
                    split4(rb[cg], &ho, &lo);
                    *(uint2*)&nb[2*TILEB + srow*MPAD + c] = ho;
                    *(uint2*)&nb[3*TILEB + srow*MPAD + c] = lo;
                }
            }
            __syncthreads();
        }

        // epilogue: warp tile 16x64
        const int g  = lane >> 2;
        const int cc = (lane & 3) * 2;
#pragma unroll
        for (int nt = 0; nt < 8; nt++){
            int n = n0 + wc*64 + nt*8 + cc;
            float b0 = fc1b[n]   + fc2b[n];
            float b1 = fc1b[n+1] + fc2b[n+1];
            int r0 = m0 + wr*16 + g;
#pragma unroll
            for (int rr2 = 0; rr2 < 2; rr2++){
                int m = r0 + rr2*8;
                float v0 = acc[nt][rr2*2]   + b0;
                float v1 = acc[nt][rr2*2+1] + b1;
                *(float2*)&g_co[(size_t)m*512 + n] = make_float2(v0, v1);
                __nv_bfloat16 h0 = __float2bfloat16(v0);
                __nv_bfloat16 h1 = __float2bfloat16(v1);
                __nv_bfloat16 l0 = __float2bfloat16(v0 - __bfloat162float(h0));
                __nv_bfloat16 l1 = __float2bfloat16(v1 - __bfloat162float(h1));
                __nv_bfloat16 hp[2] = {h0, h1}, lp[2] = {l0, l1};
                *(unsigned*)&g_cohi[(size_t)m*512 + n] = *(unsigned*)hp;
                *(unsigned*)&g_colo[(size_t)m*512 + n] = *(unsigned*)lp;
            }
        }
    } else if (bid < 352){
        // qm: 64x64 tile, threads 0..255 active (all threads hit the syncs)
        float* As = (float*)smraw;            // stride 68
        float* Bs = As + 16*68;
        const bool act = (tid < 256);
        const int qid = bid - 256;
        const int m0  = (qid >> 3) * 64;
        const int n0  = (qid & 7) * 64;
        const int tx  = tid & 15, ty = (tid >> 4) & 15;
        const int lr0 = (tid & 255) >> 2;
        const int lc4 = (tid & 3) * 4;

        float acc[4][4] = {};
        const float* A1 = qout + (size_t)(m0 + lr0)*512 + lc4;
        const float* W1 = qmw  + (size_t)(n0 + lr0)*512 + lc4;

        for (int kt = 0; kt < 512; kt += 16){
            float4 a0, w0;
            if (act){ a0 = *(const float4*)(A1 + kt); w0 = *(const float4*)(W1 + kt); }
            __syncthreads();
            if (act){
                As[(lc4+0)*68 + lr0] = a0.x; As[(lc4+1)*68 + lr0] = a0.y;
                As[(lc4+2)*68 + lr0] = a0.z; As[(lc4+3)*68 + lr0] = a0.w;
                Bs[(lc4+0)*68 + lr0] = w0.x; Bs[(lc4+1)*68 + lr0] = w0.y;
                Bs[(lc4+2)*68 + lr0] = w0.z; Bs[(lc4+3)*68 + lr0] = w0.w;
            }
            __syncthreads();
            if (act){
#pragma unroll
                for (int k = 0; k < 16; k++){
                    float4 av = *(const float4*)&As[k*68 + ty*4];
                    float4 bv = *(const float4*)&Bs[k*68 + tx*4];
                    float aa[4] = {av.x,av.y,av.z,av.w};
                    float bb[4] = {bv.x,bv.y,bv.z,bv.w};
#pragma unroll
                    for (int i = 0; i < 4; i++)
#pragma unroll
                        for (int j = 0; j < 4; j++)
                            acc[i][j] = fmaf(aa[i], bb[j], acc[i][j]);
                }
            }
        }

        if (act){
            float4 bq = *(const float4*)&qmb[n0 + tx*4];
            float bj[4] = {bq.x,bq.y,bq.z,bq.w};
#pragma unroll
            for (int i = 0; i < 4; i++){
                int m = m0 + ty*4 + i;
                float4 o = make_float4(acc[i][0]+bj[0], acc[i][1]+bj[1],
                                       acc[i][2]+bj[2], acc[i][3]+bj[3]);
                *(float4*)&g_qm[(size_t)m*512 + n0 + tx*4] = o;
            }
        }
    } else {
        int v = (bid - 352) * 512 + tid;       // 0..196607
        if (v < 131072){
            const float* src = (v < 65536) ? rm_w : rr_w;
            __nv_bfloat16* dst = (v < 65536) ? g_wbf : (g_wbf + (size_t)512*512);
            int i = v & 65535;
            float4 f = ((const float4*)src)[i];
            __nv_bfloat162 p0 = __floats2bfloat162_rn(f.x, f.y);
            __nv_bfloat162 p1 = __floats2bfloat162_rn(f.z, f.w);
            ((uint2*)dst)[i] = make_uint2(*(unsigned*)&p0, *(unsigned*)&p1);
        } else {
            int i = v - 131072;
            float4 f = ((const float4*)dm_w)[i];
            uint2 ho, lo;
            split4(f, &ho, &lo);
            ((uint2*)g_dmhi)[i] = ho;
            ((uint2*)g_dmlo)[i] = lo;
        }
    }
}

// ---------------- codm via split-bf16 mma.sync (cp.async staging) ----------------
__global__ __launch_bounds__(256) void codm_mma(const float* __restrict__ bias)
{
    extern __shared__ __nv_bfloat16 smb[];
    __nv_bfloat16* sAh = smb;
    __nv_bfloat16* sAl = smb + TILEB;
    __nv_bfloat16* sBh = smb + 2*TILEB;
    __nv_bfloat16* sBl = smb + 3*TILEB;

    const int tid  = threadIdx.x;
    const int warp = tid >> 5, lane = tid & 31;
    const int m0 = (int)(blockIdx.x >> 2) * 128;
    const int n0 = (int)(blockIdx.x & 3) * 128;
    const int wr = warp >> 1;
    const int wc = warp & 1;

    float acc[2][8][4];
#pragma unroll
    for (int i = 0; i < 2; i++)
#pragma unroll
        for (int j = 0; j < 8; j++)
#pragma unroll
            for (int k = 0; k < 4; k++) acc[i][j][k] = 0.f;

    const int ldrow = lane & 15;
    const int ldcol = (lane >> 4) * 8;

#pragma unroll 1
    for (int kc = 0; kc < 8; kc++){
#pragma unroll
        for (int t = 0; t < 4; t++){
            int i = tid + t*256;
            int r = i >> 3, c = (i & 7) * 8;
            size_t ga = (size_t)(m0 + r)*512 + kc*64 + c;
            size_t gb = (size_t)(n0 + r)*512 + kc*64 + c;
            unsigned so = (unsigned)((r*MPAD + c) * 2);
            cpa16(s2u(sAh) + so, &g_cohi[ga]);
            cpa16(s2u(sAl) + so, &g_colo[ga]);
            cpa16(s2u(sBh) + so, &g_dmhi[gb]);
            cpa16(s2u(sBl) + so, &g_dmlo[gb]);
        }
        CPA_WAIT();
        __syncthreads();
        mma_chunk(sAh, sAl, sBh, sBl, acc, wr, wc, ldrow, ldcol);
        __syncthreads();
    }

    const int g  = lane >> 2;
    const int cc = (lane & 3) * 2;
#pragma unroll
    for (int mt = 0; mt < 2; mt++){
#pragma unroll
        for (int nt = 0; nt < 8; nt++){
            int n = n0 + wc*64 + nt*8 + cc;
            float b0 = bias[n], b1 = bias[n+1];
            int r0 = m0 + wr*32 + mt*16 + g;
            __nv_bfloat162 p0 = __floats2bfloat162_rn(acc[mt][nt][0] + b0,
                                                      acc[mt][nt][1] + b1);
            *(__nv_bfloat162*)&g_codm[(size_t)r0*512 + n] = p0;
            __nv_bfloat162 p1 = __floats2bfloat162_rn(acc[mt][nt][2] + b0,
                                                      acc[mt][nt][3] + b1);
            *(__nv_bfloat162*)&g_codm[(size_t)(r0+8)*512 + n] = p1;
        }
    }
}

// ---------------- persistent cluster scan (+ merged final_g epilogue) ----------------
__global__ void __launch_bounds__(512, 1) __cluster_dims__(4, 1, 1)
scan_cluster(const float* __restrict__ rm_b, const float* __restrict__ rr_b,
             const float* __restrict__ ms_w, const float* __restrict__ ms_b,
             const float* __restrict__ rg_w, const float* __restrict__ rg_b,
             const float* __restrict__ qg_w, const float* __restrict__ qg_b,
             const float* __restrict__ qh,   float* __restrict__ out)
{
    extern __shared__ float sm[];
    __nv_bfloat16* wc = (__nv_bfloat16*)(sm + OFF_WC);
    float* s_r   = sm + OFF_R;
    float* s_add = sm + OFF_ADD;
    float* s_trr = sm + OFF_TRR;
    float* s_lp  = sm + OFF_LP;
    float* s_lgf = sm + OFF_LGF;
    float* s_red = sm + OFF_RED;
    float* s_sw  = sm + OFF_SW;
    float* s_pt  = sm + OFF_PT;
    float* s_rn  = sm + OFF_RN;
    float* s_mw  = sm + OFF_MW;
    float* s_pb  = sm + OFF_PB;

    const int tid = threadIdx.x, lane = tid & 31, warp = tid >> 5;
    unsigned int rank; asm("mov.u32 %0, %%cluster_ctarank;" : "=r"(rank));
    const int b = blockIdx.x >> 2;

    const __nv_bfloat16* grm = g_wbf + (size_t)(rank*128)*512;
    const __nv_bfloat16* grr = g_wbf + (size_t)(512 + rank*128)*512;

    for (int idx = tid; idx < CROWS*64; idx += 512){
        int row = idx >> 6, c = idx & 63;
        const __nv_bfloat16* src = (row < 128) ? (grm + (size_t)row*512)
                                               : (grr + (size_t)(row-128)*512);
        ((uint4*)wc)[idx] = ((const uint4*)src)[c];
    }
    if (tid < 256) s_pb[tid] = (tid < 128) ? rm_b[rank*128 + tid]
                                           : rr_b[rank*128 + tid - 128];
    if (tid < 128) s_mw[tid] = ms_w[rank*128 + tid];
    s_r[tid] = 0.f;
    const float msb0 = ms_b[0];
    __syncthreads();

    for (int t = 0; t < TT; t++){
        float rreg[16];
#pragma unroll
        for (int i = 0; i < 4; i++)
            ((float4*)rreg)[i] = *(const float4*)&s_r[lane*16 + i*4];

        float qv[4] = {0.f,0.f,0.f,0.f};
        if (warp < 8 && lane < 4){
#pragma unroll
            for (int g = 0; g < 4; g++)
                qv[g] = g_qm[(size_t)(t*BB + b)*512 + rank*128 + warp*16 + g*4 + lane];
        }

        if (warp < 13){
#pragma unroll
            for (int g = 0; g < 4; g++){
                float sums[4];
#pragma unroll
                for (int q = 0; q < 4; q++){
                    const __nv_bfloat16* wp = wc + (size_t)(warp*16 + g*4 + q)*512 + lane*16;
                    uint4 u0 = *(const uint4*)wp;
                    uint4 u1 = *(const uint4*)(wp + 8);
                    sums[q] = dot16(u0, u1, rreg);
                }
#pragma unroll
                for (int q = 0; q < 4; q++) sums[q] = warp_sum(sums[q]);
                if (lane < 4){
                    float v = (lane==0)?sums[0]:(lane==1)?sums[1]:(lane==2)?sums[2]:sums[3];
                    int row = warp*16 + g*4 + lane;
                    v += s_pb[row];
                    if (warp < 8) s_add[row]       = v + qv[g];
                    else          s_trr[row - 128] = tanh_mufu(v);
                }
            }
        } else {
#pragma unroll
            for (int g = 0; g < 4; g++){
                uint4 u[4][2];
#pragma unroll
                for (int q = 0; q < 4; q++){
                    const __nv_bfloat16* wp = grr + (size_t)(warp*16 + g*4 + q - 128)*512 + lane*16;
                    u[q][0] = *(const uint4*)wp;
                    u[q][1] = *(const uint4*)(wp + 8);
                }
                float sums[4];
#pragma unroll
                for (int q = 0; q < 4; q++) sums[q] = dot16(u[q][0], u[q][1], rreg);
#pragma unroll
                for (int q = 0; q < 4; q++) sums[q] = warp_sum(sums[q]);
                if (lane < 4){
                    float v = (lane==0)?sums[0]:(lane==1)?sums[1]:(lane==2)?sums[2]:sums[3];
                    int row = warp*16 + g*4 + lane;
                    s_trr[row - 128] = tanh_mufu(v + s_pb[row]);
                }
            }
        }
        __syncthreads();

        {
            float areg[4], mreg[4];
#pragma unroll
            for (int i = 0; i < 4; i++){
                areg[i] = s_add[lane*4 + i];
                mreg[i] = s_mw[lane*4 + i];
            }
#pragma unroll
            for (int g = 0; g < 4; g++){
                int s0 = warp*16 + g*4;
                float a4[4];
#pragma unroll
                for (int q = 0; q < 4; q++){
                    const __nv_bfloat16* cd = g_codm + (size_t)(b*256 + s0 + q)*512
                                            + rank*128 + lane*4;
                    uint2 u = *(const uint2*)cd;
                    float2 c01 = __bfloat1622float2(*(const __nv_bfloat162*)&u.x);
                    float2 c23 = __bfloat1622float2(*(const __nv_bfloat162*)&u.y);
                    a4[q] = tanh_mufu(c01.x + areg[0]) * mreg[0]
                          + tanh_mufu(c01.y + areg[1]) * mreg[1]
                          + tanh_mufu(c23.x + areg[2]) * mreg[2]
                          + tanh_mufu(c23.y + areg[3]) * mreg[3];
                }
#pragma unroll
                for (int q = 0; q < 4; q++) a4[q] = warp_sum(a4[q]);
                if (lane < 4){
                    float v = (lane==0)?a4[0]:(lane==1)?a4[1]:(lane==2)?a4[2]:a4[3];
                    s_lp[s0 + lane] = v;
                }
            }
        }
        CLUSTER_SYNC();

        if (tid < 256){
            unsigned int sa = s2u(&s_lp[tid]);
            float v = s_lp[tid] + msb0
                    + dsmem_ld(sa, (rank+1)&3u)
                    + dsmem_ld(sa, (rank+2)&3u)
                    + dsmem_ld(sa, (rank+3)&3u);
            s_lgf[tid] = v;
        }
        __syncthreads();

        {
            float l = s_lgf[tid & 255];
            float m = l;
#pragma unroll
            for (int o = 16; o; o >>= 1) m = fmaxf(m, __shfl_xor_sync(0xffffffffu, m, o));
            if (lane == 0) s_red[warp] = m;
            __syncthreads();
            float mx = s_red[0];
#pragma unroll
            for (int i = 1; i < 16; i++) mx = fmaxf(mx, s_red[i]);
            float ex = __expf(l - mx);
            float smm = warp_sum(ex);
            if (lane == 0) s_red[16 + warp] = smm;
            __syncthreads();
            float tot = s_red[16];
#pragma unroll
            for (int i = 17; i < 32; i++) tot += s_red[i];
            tot *= 0.5f;
            s_sw[tid & 255] = ex * (1.0f / tot);
        }
        __syncthreads();

        {
            int e  = (int)rank*128 + (tid & 127);
            int sq = tid >> 7;
            const float* cb = g_co + (size_t)(b*256 + sq*64)*512 + e;
            const float* wv = s_sw + sq*64;
            float acc = 0.f;
#pragma unroll 16
            for (int s = 0; s < 64; s++)
                acc = fmaf(wv[s], cb[(size_t)s*512], acc);
            s_pt[tid] = acc;
            __syncthreads();
            if (tid < 128){
                float v = s_pt[tid] + s_pt[tid+128] + s_pt[tid+256] + s_pt[tid+384]
                        + s_trr[tid];
                s_rn[tid] = v;
            }
        }
        CLUSTER_SYNC();

        if (t < TT-1){
            s_r[tid] = dsmem_ld(s2u(&s_rn[tid & 127]), (unsigned int)(tid >> 7));
            __syncthreads();
        }
    }

    // ===== merged final_g =====
    {
        s_r[tid] = dsmem_ld(s2u(&s_rn[tid & 127]), (unsigned int)(tid >> 7));
        float* s_qh = s_lp;
        s_qh[tid] = qh[b*512 + tid];
        __syncthreads();

#pragma unroll 1
        for (int i = 0; i < 8; i++){
            int e = (int)rank*128 + warp*8 + i;
            const float* w1 = rg_w + (size_t)e*512;
            const float* w2 = qg_w + (size_t)e*512;
            float s = 0.f;
#pragma unroll
            for (int j = 0; j < 4; j++){
                int k = j*128 + lane*4;
                float4 a = *(const float4*)(w1 + k);
                float4 x = *(const float4*)(s_r + k);
                float4 c = *(const float4*)(w2 + k);
                float4 y = *(const float4*)(s_qh + k);
                s += a.x*x.x + a.y*x.y + a.z*x.z + a.w*x.w;
                s += c.x*y.x + c.y*y.y + c.z*y.z + c.w*y.w;
            }
            s = warp_sum(s);
            if (lane == 0) out[b*512 + e] = s + rg_b[e] + qg_b[e];
        }
    }

    CLUSTER_SYNC();
}

// ---------------- host launch ----------------
extern "C" void kernel_launch(void* const* d_in, const int* in_sizes, int n_in,
                              void* d_out, int out_size)
{
    const float* ctx  = (const float*)d_in[0];
    const float* qout = (const float*)d_in[2];
    const float* qh   = (const float*)d_in[3];
    const float* img  = (const float*)d_in[4];
    const float* fc1w = (const float*)d_in[6];  const float* fc1b = (const float*)d_in[7];
    const float* fc2w = (const float*)d_in[8];  const float* fc2b = (const float*)d_in[9];
    const float* dmw  = (const float*)d_in[10]; const float* dmb  = (const float*)d_in[11];
    const float* msw  = (const float*)d_in[12]; const float* msb  = (const float*)d_in[13];
    const float* rmw  = (const float*)d_in[14]; const float* rmb  = (const float*)d_in[15];
    const float* qmw  = (const float*)d_in[16]; const float* qmb  = (const float*)d_in[17];
    const float* rrw  = (const float*)d_in[18]; const float* rrb  = (const float*)d_in[19];
    const float* rgw  = (const float*)d_in[20]; const float* rgb  = (const float*)d_in[21];
    const float* qgw  = (const float*)d_in[22]; const float* qgb  = (const float*)d_in[23];

    cudaFuncSetAttribute(scan_cluster, cudaFuncAttributeMaxDynamicSharedMemorySize,
                         SMEM_SCAN_BYTES);
    cudaFuncSetAttribute(codm_mma, cudaFuncAttributeMaxDynamicSharedMemorySize,
                         MMA_SMEM_BYTES);
    cudaFuncSetAttribute(gemm_A, cudaFuncAttributeMaxDynamicSharedMemorySize,
                         MMA2_SMEM_BYTES);

    // MEGA launch: co (pipelined split-HMMA) + qm GEMM + conversions
    gemm_A<<<736, 512, MMA2_SMEM_BYTES>>>(ctx, img, fc1w, fc1b, fc2w, fc2b,
                                          qout, qmw, qmb, rmw, rrw, dmw);

    // codm = co @ dm_w^T + dm_b via split-bf16 HMMA (cp.async staging)
    codm_mma<<<256, 256, MMA_SMEM_BYTES>>>(dmb);

    // scan (incl. merged final output projection)
    scan_cluster<<<128, 512, SMEM_SCAN_BYTES>>>(rmb, rrb, msw, msb,
                                                rgw, rgb, qgw, qgb, qh,
                                                (float*)d_out);
}